// round 2
// baseline (speedup 1.0000x reference)
#include <cuda_runtime.h>
#include <math.h>

#define D 128
#define MAXN 65536
#define MAXE 1100000

// Scratch (allocation-free rule: __device__ globals)
__device__ float g_xtan[MAXN * D];
__device__ float g_xlin[MAXN * D];
__device__ float g_agg[MAXN * D];
__device__ float g_x[MAXN * D];
__device__ float g_cnt[MAXN];
__device__ int   g_src[MAXE];
__device__ int   g_dst[MAXE];
__device__ int   g_is64;

__device__ __forceinline__ float warp_sum(float v) {
#pragma unroll
    for (int o = 16; o; o >>= 1) v += __shfl_xor_sync(0xFFFFFFFFu, v, o);
    return v;
}

__device__ __forceinline__ float clip_c(float c) {
    return fminf(fmaxf(c, 0.1f), 10.0f);
}

// ---------------------------------------------------------------------------
// Detect edge-index dtype: int64 vs int32 (JAX may silently emit int32).
// Reads first 1024 int64 words (safe under both interpretations for E>=1024).
// ---------------------------------------------------------------------------
__global__ void k_detect(const long long* __restrict__ ei, int E, long long N) {
    if (threadIdx.x != 0 || blockIdx.x != 0) return;
    int n = E < 1024 ? E : 1024;
    int ok64 = 1;
    for (int i = 0; i < n; i++) {
        long long v = ei[i];
        if (v < 0 || v >= N) { ok64 = 0; break; }
    }
    g_is64 = ok64;
}

// ---------------------------------------------------------------------------
// Convert edge index to int32 src/dst (clamped) + in-degree histogram.
// ---------------------------------------------------------------------------
__global__ void k_convert(const void* __restrict__ ei, int* __restrict__ src,
                          int* __restrict__ dst, float* __restrict__ cnt,
                          int E, int N) {
    int e = blockIdx.x * blockDim.x + threadIdx.x;
    if (e >= E) return;
    long long s, d;
    if (g_is64) {
        const long long* p = (const long long*)ei;
        s = p[e];
        d = p[(size_t)E + e];
    } else {
        const int* p = (const int*)ei;
        s = p[e];
        d = p[(size_t)E + e];
    }
    int si = (int)min(max(s, 0LL), (long long)(N - 1));
    int di = (int)min(max(d, 0LL), (long long)(N - 1));
    src[e] = si;
    dst[e] = di;
    atomicAdd(&cnt[di], 1.0f);
}

// ---------------------------------------------------------------------------
// log_map_zero: one warp per row, float4 per lane (32*4 = 128)
// ---------------------------------------------------------------------------
__global__ void k_logmap(const float* __restrict__ x, float* __restrict__ xt,
                         const float* __restrict__ curv, int l, int N) {
    int w = (blockIdx.x * blockDim.x + threadIdx.x) >> 5;
    int lane = threadIdx.x & 31;
    if (w >= N) return;
    float c = clip_c(curv[l]);
    float K = 1.0f / c;
    float sqrtK = sqrtf(K);
    float4 v = reinterpret_cast<const float4*>(x + (size_t)w * D)[lane];
    float ss = v.x * v.x + v.y * v.y + v.z * v.z + v.w * v.w;
    ss = warp_sum(ss);
    float xnorm = sqrtf(ss);
    float t = sqrtf(K + ss);
    float theta = acoshf(fmaxf(t / sqrtK, 1.0f + 1e-7f));
    float s = sqrtK * theta / fmaxf(xnorm, 1e-7f);
    float4 o = make_float4(v.x * s, v.y * s, v.z * s, v.w * s);
    reinterpret_cast<float4*>(xt + (size_t)w * D)[lane] = o;
}

// ---------------------------------------------------------------------------
// GEMM: x_lin[n,j] = sum_k x_tan[n,k] * W[j,k] + b[j]
// Block: 16 rows x 128 cols, 256 threads, each thread: col j, 8 rows.
// W staged in SMEM per 64-k chunk with XOR swizzle (conflict-free both ways).
// ---------------------------------------------------------------------------
__global__ void k_gemm(const float* __restrict__ xt, const float* __restrict__ W,
                       const float* __restrict__ b, float* __restrict__ xl, int N) {
    __shared__ float xs[16][D];     // 8 KB
    __shared__ float ws[64 * D];    // 32 KB, ws[kk*128 + (j ^ (kk&31))] = W[j][kc*64+kk]
    int tid = threadIdx.x;
    int row0 = blockIdx.x * 16;
    int j = tid & 127;
    int r0 = (tid >> 7) * 8;

    // load 16 rows of x_tan (512 float4)
    {
        const float4* src = reinterpret_cast<const float4*>(xt + (size_t)row0 * D);
        float4* dstp = reinterpret_cast<float4*>(&xs[0][0]);
        for (int i = tid; i < 512; i += 256) {
            int r = i >> 5;
            dstp[i] = (row0 + r < N) ? src[i] : make_float4(0.f, 0.f, 0.f, 0.f);
        }
    }

    float acc[8];
#pragma unroll
    for (int r = 0; r < 8; r++) acc[r] = 0.0f;

    for (int kc = 0; kc < 2; kc++) {
        __syncthreads();
        // stage W chunk: global coalesced over kk, smem conflict-free via XOR swizzle
        for (int i = tid; i < 64 * D; i += 256) {
            int jj = i >> 6;
            int kk = i & 63;
            ws[kk * D + (jj ^ (kk & 31))] = W[jj * D + kc * 64 + kk];
        }
        __syncthreads();
#pragma unroll
        for (int k4 = 0; k4 < 16; k4++) {
            float4 xv[8];
#pragma unroll
            for (int r = 0; r < 8; r++)
                xv[r] = *reinterpret_cast<const float4*>(&xs[r0 + r][kc * 64 + k4 * 4]);
#pragma unroll
            for (int q = 0; q < 4; q++) {
                int kk = k4 * 4 + q;
                float wv = ws[kk * D + (j ^ (kk & 31))];
                const float* xp;
#pragma unroll
                for (int r = 0; r < 8; r++) {
                    xp = reinterpret_cast<const float*>(&xv[r]);
                    acc[r] += xp[q] * wv;
                }
            }
        }
    }

    float bj = b[j];
#pragma unroll
    for (int r = 0; r < 8; r++) {
        int rr = row0 + r0 + r;
        if (rr < N) xl[(size_t)rr * D + j] = acc[r] + bj;
    }
}

// ---------------------------------------------------------------------------
// scatter-add: one warp per edge, float4 per lane, vectorized RED (sm_90+)
// ---------------------------------------------------------------------------
__global__ void k_scatter(const int* __restrict__ src, const int* __restrict__ dst,
                          const float* __restrict__ xl, float* __restrict__ agg, int E) {
    int w = (blockIdx.x * blockDim.x + threadIdx.x) >> 5;
    int lane = threadIdx.x & 31;
    if (w >= E) return;
    int s = __ldg(&src[w]);
    int d = __ldg(&dst[w]);
    float4 v = __ldg(reinterpret_cast<const float4*>(xl + (size_t)s * D) + lane);
    float* p = agg + (size_t)d * D + lane * 4;
    asm volatile("red.global.add.v4.f32 [%0], {%1, %2, %3, %4};"
                 :: "l"(p), "f"(v.x), "f"(v.y), "f"(v.z), "f"(v.w)
                 : "memory");
}

// ---------------------------------------------------------------------------
// residual + layernorm + exp_map: one warp per row
// ---------------------------------------------------------------------------
__global__ void k_final(const float* __restrict__ xt, const float* __restrict__ agg,
                        const float* __restrict__ cnt,
                        const float* __restrict__ gamma, const float* __restrict__ beta,
                        const float* __restrict__ curv, int l,
                        float* __restrict__ out, int N) {
    int w = (blockIdx.x * blockDim.x + threadIdx.x) >> 5;
    int lane = threadIdx.x & 31;
    if (w >= N) return;
    float c = clip_c(curv[l]);
    float K = 1.0f / c;
    float sqrtK = sqrtf(K);
    float cn = fmaxf(cnt[w], 1.0f);
    float rcn = 1.0f / cn;

    float4 t = reinterpret_cast<const float4*>(xt + (size_t)w * D)[lane];
    float4 a = reinterpret_cast<const float4*>(agg + (size_t)w * D)[lane];
    float4 v = make_float4(t.x + a.x * rcn, t.y + a.y * rcn,
                           t.z + a.z * rcn, t.w + a.w * rcn);

    float s1 = v.x + v.y + v.z + v.w;
    float s2 = v.x * v.x + v.y * v.y + v.z * v.z + v.w * v.w;
    s1 = warp_sum(s1);
    s2 = warp_sum(s2);
    float mean = s1 * (1.0f / D);
    float var = s2 * (1.0f / D) - mean * mean;
    float rstd = rsqrtf(var + 1e-5f);

    float4 g = reinterpret_cast<const float4*>(gamma)[lane];
    float4 bb = reinterpret_cast<const float4*>(beta)[lane];
    float4 y = make_float4((v.x - mean) * rstd * g.x + bb.x,
                           (v.y - mean) * rstd * g.y + bb.y,
                           (v.z - mean) * rstd * g.z + bb.z,
                           (v.w - mean) * rstd * g.w + bb.w);

    float ss = y.x * y.x + y.y * y.y + y.z * y.z + y.w * y.w;
    ss = warp_sum(ss);
    float vnorm = sqrtf(ss);
    float sc = sqrtK * sinhf(vnorm / sqrtK) / fmaxf(vnorm, 1e-7f);

    float4 o = make_float4(y.x * sc, y.y * sc, y.z * sc, y.w * sc);
    reinterpret_cast<float4*>(out + (size_t)w * D)[lane] = o;
}

// ---------------------------------------------------------------------------
extern "C" void kernel_launch(void* const* d_in, const int* in_sizes, int n_in,
                              void* d_out, int out_size) {
    const float* x_hyp      = (const float*)d_in[0];
    const void*  ei         = d_in[1];
    const float* W          = (const float*)d_in[2];
    const float* b          = (const float*)d_in[3];
    const float* gamma      = (const float*)d_in[4];
    const float* beta       = (const float*)d_in[5];
    const float* curv       = (const float*)d_in[6];

    int N = in_sizes[0] / D;
    int E = in_sizes[1] / 2;
    int L = in_sizes[6];

    float *xtan, *xlin, *agg, *xbuf, *cnt;
    int *srcp, *dstp;
    cudaGetSymbolAddress((void**)&xtan, g_xtan);
    cudaGetSymbolAddress((void**)&xlin, g_xlin);
    cudaGetSymbolAddress((void**)&agg,  g_agg);
    cudaGetSymbolAddress((void**)&xbuf, g_x);
    cudaGetSymbolAddress((void**)&cnt,  g_cnt);
    cudaGetSymbolAddress((void**)&srcp, g_src);
    cudaGetSymbolAddress((void**)&dstp, g_dst);

    // edge-index dtype detection + conversion + in-degree counts (once per call)
    cudaMemsetAsync(cnt, 0, (size_t)N * sizeof(float));
    k_detect<<<1, 32>>>((const long long*)ei, E, (long long)N);
    k_convert<<<(E + 255) / 256, 256>>>(ei, srcp, dstp, cnt, E, N);

    int rowBlocks = (N * 32 + 255) / 256;        // warp-per-row kernels
    long long scatterThreads = (long long)E * 32;
    int scatterBlocks = (int)((scatterThreads + 255) / 256);

    const float* xin = x_hyp;
    for (int l = 0; l < L; l++) {
        k_logmap<<<rowBlocks, 256>>>(xin, xtan, curv, l, N);
        k_gemm<<<(N + 15) / 16, 256>>>(xtan, W + (size_t)l * D * D, b + (size_t)l * D, xlin, N);
        cudaMemsetAsync(agg, 0, (size_t)N * D * sizeof(float));
        k_scatter<<<scatterBlocks, 256>>>(srcp, dstp, xlin, agg, E);
        float* out = (l == L - 1) ? (float*)d_out : xbuf;
        k_final<<<rowBlocks, 256>>>(xtan, agg, cnt,
                                    gamma + (size_t)l * D, beta + (size_t)l * D,
                                    curv, l, out, N);
        xin = xbuf;
    }
}

// round 4
// speedup vs baseline: 1.6245x; 1.6245x over previous
#include <cuda_runtime.h>
#include <math.h>

#define D 128
#define MAXN 65536
#define MAXE 1100000

// Scratch (allocation-free rule: __device__ globals)
__device__ float g_xtan[MAXN * D];
__device__ float g_xlin[MAXN * D];
__device__ float g_x[MAXN * D];
__device__ int   g_deg[MAXN];
__device__ int   g_rowstart[MAXN + 1];
__device__ int   g_cursor[MAXN];
__device__ int   g_incl[MAXN];
__device__ int   g_bsum[512];
__device__ int   g_src[MAXE];
__device__ int   g_dst[MAXE];
__device__ int   g_csr[MAXE];
__device__ int   g_is64;

__device__ __forceinline__ float warp_sum(float v) {
#pragma unroll
    for (int o = 16; o; o >>= 1) v += __shfl_xor_sync(0xFFFFFFFFu, v, o);
    return v;
}

__device__ __forceinline__ float clip_c(float c) {
    return fminf(fmaxf(c, 0.1f), 10.0f);
}

// ---------------------------------------------------------------------------
// Detect edge-index dtype: int64 vs int32 (JAX may silently emit int32).
// ---------------------------------------------------------------------------
__global__ void k_detect(const long long* __restrict__ ei, int E, long long N) {
    if (threadIdx.x != 0 || blockIdx.x != 0) return;
    int n = E < 1024 ? E : 1024;
    int ok64 = 1;
    for (int i = 0; i < n; i++) {
        long long v = ei[i];
        if (v < 0 || v >= N) { ok64 = 0; break; }
    }
    g_is64 = ok64;
}

// ---------------------------------------------------------------------------
// Convert edge index to int32 src/dst (clamped) + in-degree histogram (int).
// ---------------------------------------------------------------------------
__global__ void k_convert(const void* __restrict__ ei, int* __restrict__ src,
                          int* __restrict__ dst, int* __restrict__ deg,
                          int E, int N) {
    int e = blockIdx.x * blockDim.x + threadIdx.x;
    if (e >= E) return;
    long long s, d;
    if (g_is64) {
        const long long* p = (const long long*)ei;
        s = p[e];
        d = p[(size_t)E + e];
    } else {
        const int* p = (const int*)ei;
        s = p[e];
        d = p[(size_t)E + e];
    }
    int si = (int)min(max(s, 0LL), (long long)(N - 1));
    int di = (int)min(max(d, 0LL), (long long)(N - 1));
    src[e] = si;
    dst[e] = di;
    atomicAdd(&deg[di], 1);
}

// ---------------------------------------------------------------------------
// 3-phase prefix scan over deg[] -> rowstart[] (exclusive, rowstart[0]=0)
// ---------------------------------------------------------------------------
__global__ void k_scanA(const int* __restrict__ deg, int* __restrict__ incl,
                        int* __restrict__ bsum, int N) {
    __shared__ int wsum[8];
    int tid = threadIdx.x, lane = tid & 31, warp = tid >> 5;
    int gid = blockIdx.x * 256 + tid;
    int v = (gid < N) ? deg[gid] : 0;
    int x = v;
#pragma unroll
    for (int o = 1; o < 32; o <<= 1) {
        int y = __shfl_up_sync(0xFFFFFFFFu, x, o);
        if (lane >= o) x += y;
    }
    if (lane == 31) wsum[warp] = x;
    __syncthreads();
    if (warp == 0) {
        int s = (lane < 8) ? wsum[lane] : 0;
        int y = s;
#pragma unroll
        for (int o = 1; o < 8; o <<= 1) {
            int z = __shfl_up_sync(0xFFFFFFFFu, y, o);
            if (lane >= o) y += z;
        }
        if (lane < 8) wsum[lane] = y - s;   // exclusive warp offset
    }
    __syncthreads();
    int inclv = x + wsum[warp];
    if (gid < N) incl[gid] = inclv;
    if (tid == 255) bsum[blockIdx.x] = inclv;
}

__global__ void k_scanB(int* __restrict__ bsum, int nb) {
    __shared__ int wsum[8];
    int tid = threadIdx.x, lane = tid & 31, warp = tid >> 5;
    int v = (tid < nb) ? bsum[tid] : 0;
    int x = v;
#pragma unroll
    for (int o = 1; o < 32; o <<= 1) {
        int y = __shfl_up_sync(0xFFFFFFFFu, x, o);
        if (lane >= o) x += y;
    }
    if (lane == 31) wsum[warp] = x;
    __syncthreads();
    if (warp == 0) {
        int s = (lane < 8) ? wsum[lane] : 0;
        int y = s;
#pragma unroll
        for (int o = 1; o < 8; o <<= 1) {
            int z = __shfl_up_sync(0xFFFFFFFFu, y, o);
            if (lane >= o) y += z;
        }
        if (lane < 8) wsum[lane] = y - s;
    }
    __syncthreads();
    if (tid < nb) bsum[tid] = x + wsum[warp] - v;   // exclusive block offset
}

__global__ void k_scanC(const int* __restrict__ incl, const int* __restrict__ bsum,
                        int* __restrict__ rowstart, int N) {
    int gid = blockIdx.x * 256 + threadIdx.x;
    if (gid == 0) rowstart[0] = 0;
    if (gid < N) rowstart[gid + 1] = incl[gid] + bsum[blockIdx.x];
}

__global__ void k_fill(const int* __restrict__ src, const int* __restrict__ dst,
                       const int* __restrict__ rowstart, int* __restrict__ cursor,
                       int* __restrict__ csr, int E) {
    int e = blockIdx.x * blockDim.x + threadIdx.x;
    if (e >= E) return;
    int d = dst[e];
    int pos = rowstart[d] + atomicAdd(&cursor[d], 1);
    csr[pos] = src[e];
}

// ---------------------------------------------------------------------------
// log_map_zero: one warp per row, float4 per lane (32*4 = 128)
// ---------------------------------------------------------------------------
__global__ void k_logmap(const float* __restrict__ x, float* __restrict__ xt,
                         const float* __restrict__ curv, int l, int N) {
    int w = (blockIdx.x * blockDim.x + threadIdx.x) >> 5;
    int lane = threadIdx.x & 31;
    if (w >= N) return;
    float c = clip_c(curv[l]);
    float K = 1.0f / c;
    float sqrtK = sqrtf(K);
    float4 v = reinterpret_cast<const float4*>(x + (size_t)w * D)[lane];
    float ss = v.x * v.x + v.y * v.y + v.z * v.z + v.w * v.w;
    ss = warp_sum(ss);
    float xnorm = sqrtf(ss);
    float t = sqrtf(K + ss);
    float theta = acoshf(fmaxf(t / sqrtK, 1.0f + 1e-7f));
    float s = sqrtK * theta / fmaxf(xnorm, 1e-7f);
    float4 o = make_float4(v.x * s, v.y * s, v.z * s, v.w * s);
    reinterpret_cast<float4*>(xt + (size_t)w * D)[lane] = o;
}

// ---------------------------------------------------------------------------
// GEMM v2.1: x_lin = x_tan @ W^T + b. Tile 32 rows x 128 cols, 256 threads,
// each thread owns a 4x4 register tile. W staged k-major in smem with
// 136-float row pitch (conflict-free float4 reads). x reads are warp
// broadcasts. FIX: x fragment read now includes the kc*32 chunk offset.
// ---------------------------------------------------------------------------
__global__ void __launch_bounds__(256) k_gemm(
        const float* __restrict__ xt, const float* __restrict__ W,
        const float* __restrict__ b, float* __restrict__ xl, int N) {
    __shared__ float xs[32][D];        // 16 KB
    __shared__ float ws[32][136];      // 17.4 KB, ws[kk][j] = W[j][kc*32+kk]
    int tid = threadIdx.x;
    int row0 = blockIdx.x * 32;
    int r0 = (tid >> 5) * 4;           // warp -> 4 rows
    int c0 = (tid & 31) * 4;           // lane -> 4 cols

    // load 32 rows of x_tan (1024 float4)
    {
        const float4* srcp = reinterpret_cast<const float4*>(xt + (size_t)row0 * D);
        float4* dstp = reinterpret_cast<float4*>(&xs[0][0]);
        for (int i = tid; i < 1024; i += 256) {
            int r = i >> 5;
            dstp[i] = (row0 + r < N) ? srcp[i] : make_float4(0.f, 0.f, 0.f, 0.f);
        }
    }

    float acc[4][4];
#pragma unroll
    for (int r = 0; r < 4; r++)
#pragma unroll
        for (int c = 0; c < 4; c++) acc[r][c] = 0.0f;

    for (int kc = 0; kc < 4; kc++) {
        __syncthreads();
        // stage ws[kk][j] = W[j][kc*32+kk]; coalesced global (128B per 4 rows)
#pragma unroll
        for (int p = 0; p < 4; p++) {
            int j = (tid >> 3) + p * 32;
            int kg = (tid & 7) * 4;
            float4 w4 = *reinterpret_cast<const float4*>(&W[(size_t)j * D + kc * 32 + kg]);
            ws[kg + 0][j] = w4.x;
            ws[kg + 1][j] = w4.y;
            ws[kg + 2][j] = w4.z;
            ws[kg + 3][j] = w4.w;
        }
        __syncthreads();
#pragma unroll
        for (int k4 = 0; k4 < 8; k4++) {
            float4 xv[4], wv[4];
#pragma unroll
            for (int r = 0; r < 4; r++)
                xv[r] = *reinterpret_cast<const float4*>(&xs[r0 + r][kc * 32 + k4 * 4]);
#pragma unroll
            for (int q = 0; q < 4; q++)
                wv[q] = *reinterpret_cast<const float4*>(&ws[k4 * 4 + q][c0]);
#pragma unroll
            for (int r = 0; r < 4; r++) {
                const float* xp = reinterpret_cast<const float*>(&xv[r]);
#pragma unroll
                for (int q = 0; q < 4; q++) {
                    acc[r][0] += xp[q] * wv[q].x;
                    acc[r][1] += xp[q] * wv[q].y;
                    acc[r][2] += xp[q] * wv[q].z;
                    acc[r][3] += xp[q] * wv[q].w;
                }
            }
        }
    }

    float4 bb = *reinterpret_cast<const float4*>(&b[c0]);
#pragma unroll
    for (int r = 0; r < 4; r++) {
        int rr = row0 + r0 + r;
        if (rr < N) {
            float4 o = make_float4(acc[r][0] + bb.x, acc[r][1] + bb.y,
                                   acc[r][2] + bb.z, acc[r][3] + bb.w);
            *reinterpret_cast<float4*>(&xl[(size_t)rr * D + c0]) = o;
        }
    }
}

// ---------------------------------------------------------------------------
// Fused CSR aggregation (gather, no atomics) + mean + residual + LN + expmap.
// One warp per destination row.
// ---------------------------------------------------------------------------
__global__ void k_aggfinal(const int* __restrict__ rowstart, const int* __restrict__ csr,
                           const float* __restrict__ xl, const float* __restrict__ xt,
                           const int* __restrict__ deg,
                           const float* __restrict__ gamma, const float* __restrict__ beta,
                           const float* __restrict__ curv, int l,
                           float* __restrict__ out, int N) {
    int w = (blockIdx.x * blockDim.x + threadIdx.x) >> 5;
    int lane = threadIdx.x & 31;
    if (w >= N) return;

    int beg = rowstart[w];
    int end = rowstart[w + 1];
    float4 acc = make_float4(0.f, 0.f, 0.f, 0.f);

    int e = beg;
    for (; e + 4 <= end; e += 4) {
        int s0 = __ldg(&csr[e + 0]);
        int s1 = __ldg(&csr[e + 1]);
        int s2 = __ldg(&csr[e + 2]);
        int s3 = __ldg(&csr[e + 3]);
        float4 a0 = __ldg(reinterpret_cast<const float4*>(xl + (size_t)s0 * D) + lane);
        float4 a1 = __ldg(reinterpret_cast<const float4*>(xl + (size_t)s1 * D) + lane);
        float4 a2 = __ldg(reinterpret_cast<const float4*>(xl + (size_t)s2 * D) + lane);
        float4 a3 = __ldg(reinterpret_cast<const float4*>(xl + (size_t)s3 * D) + lane);
        acc.x += (a0.x + a1.x) + (a2.x + a3.x);
        acc.y += (a0.y + a1.y) + (a2.y + a3.y);
        acc.z += (a0.z + a1.z) + (a2.z + a3.z);
        acc.w += (a0.w + a1.w) + (a2.w + a3.w);
    }
    for (; e < end; e++) {
        int s = __ldg(&csr[e]);
        float4 a = __ldg(reinterpret_cast<const float4*>(xl + (size_t)s * D) + lane);
        acc.x += a.x; acc.y += a.y; acc.z += a.z; acc.w += a.w;
    }

    float c = clip_c(curv[l]);
    float K = 1.0f / c;
    float sqrtK = sqrtf(K);
    int dg = deg[w];
    float rcn = 1.0f / (float)(dg > 1 ? dg : 1);

    float4 t = reinterpret_cast<const float4*>(xt + (size_t)w * D)[lane];
    float4 v = make_float4(t.x + acc.x * rcn, t.y + acc.y * rcn,
                           t.z + acc.z * rcn, t.w + acc.w * rcn);

    float s1 = v.x + v.y + v.z + v.w;
    float s2 = v.x * v.x + v.y * v.y + v.z * v.z + v.w * v.w;
    s1 = warp_sum(s1);
    s2 = warp_sum(s2);
    float mean = s1 * (1.0f / D);
    float var = s2 * (1.0f / D) - mean * mean;
    float rstd = rsqrtf(var + 1e-5f);

    float4 g = reinterpret_cast<const float4*>(gamma)[lane];
    float4 bb = reinterpret_cast<const float4*>(beta)[lane];
    float4 y = make_float4((v.x - mean) * rstd * g.x + bb.x,
                           (v.y - mean) * rstd * g.y + bb.y,
                           (v.z - mean) * rstd * g.z + bb.z,
                           (v.w - mean) * rstd * g.w + bb.w);

    float ss = y.x * y.x + y.y * y.y + y.z * y.z + y.w * y.w;
    ss = warp_sum(ss);
    float vnorm = sqrtf(ss);
    float sc = sqrtK * sinhf(vnorm / sqrtK) / fmaxf(vnorm, 1e-7f);

    float4 o = make_float4(y.x * sc, y.y * sc, y.z * sc, y.w * sc);
    reinterpret_cast<float4*>(out + (size_t)w * D)[lane] = o;
}

// ---------------------------------------------------------------------------
extern "C" void kernel_launch(void* const* d_in, const int* in_sizes, int n_in,
                              void* d_out, int out_size) {
    const float* x_hyp      = (const float*)d_in[0];
    const void*  ei         = d_in[1];
    const float* W          = (const float*)d_in[2];
    const float* b          = (const float*)d_in[3];
    const float* gamma      = (const float*)d_in[4];
    const float* beta       = (const float*)d_in[5];
    const float* curv       = (const float*)d_in[6];

    int N = in_sizes[0] / D;
    int E = in_sizes[1] / 2;
    int L = in_sizes[6];

    float *xtan, *xlin, *xbuf;
    int *deg, *rowstart, *cursor, *incl, *bsum, *srcp, *dstp, *csr;
    cudaGetSymbolAddress((void**)&xtan, g_xtan);
    cudaGetSymbolAddress((void**)&xlin, g_xlin);
    cudaGetSymbolAddress((void**)&xbuf, g_x);
    cudaGetSymbolAddress((void**)&deg,  g_deg);
    cudaGetSymbolAddress((void**)&rowstart, g_rowstart);
    cudaGetSymbolAddress((void**)&cursor, g_cursor);
    cudaGetSymbolAddress((void**)&incl, g_incl);
    cudaGetSymbolAddress((void**)&bsum, g_bsum);
    cudaGetSymbolAddress((void**)&srcp, g_src);
    cudaGetSymbolAddress((void**)&dstp, g_dst);
    cudaGetSymbolAddress((void**)&csr,  g_csr);

    int nb = (N + 255) / 256;

    // One-time per call: dtype detect, convert + degree, scan, CSR fill.
    cudaMemsetAsync(deg, 0, (size_t)N * sizeof(int));
    cudaMemsetAsync(cursor, 0, (size_t)N * sizeof(int));
    k_detect<<<1, 32>>>((const long long*)ei, E, (long long)N);
    k_convert<<<(E + 255) / 256, 256>>>(ei, srcp, dstp, deg, E, N);
    k_scanA<<<nb, 256>>>(deg, incl, bsum, N);
    k_scanB<<<1, 256>>>(bsum, nb);
    k_scanC<<<nb, 256>>>(incl, bsum, rowstart, N);
    k_fill<<<(E + 255) / 256, 256>>>(srcp, dstp, rowstart, cursor, csr, E);

    int rowBlocks = (N * 32 + 255) / 256;        // warp-per-row kernels

    const float* xin = x_hyp;
    for (int l = 0; l < L; l++) {
        k_logmap<<<rowBlocks, 256>>>(xin, xtan, curv, l, N);
        k_gemm<<<(N + 31) / 32, 256>>>(xtan, W + (size_t)l * D * D, b + (size_t)l * D, xlin, N);
        float* out = (l == L - 1) ? (float*)d_out : xbuf;
        k_aggfinal<<<rowBlocks, 256>>>(rowstart, csr, xlin, xtan, deg,
                                       gamma + (size_t)l * D, beta + (size_t)l * D,
                                       curv, l, out, N);
        xin = xbuf;
    }
}

// round 6
// speedup vs baseline: 1.8058x; 1.1116x over previous
#include <cuda_runtime.h>
#include <cuda_fp16.h>
#include <math.h>

#define D 128
#define MAXN 65536
#define MAXE 1100000

// Scratch (allocation-free rule: __device__ globals)
__device__ float   g_xtan[MAXN * D];
__device__ float   g_x[MAXN * D];
__device__ __half2 g_xl16[MAXN * (D / 2)];
__device__ int     g_deg[MAXN];
__device__ int     g_rowstart[MAXN + 1];
__device__ int     g_cursor[MAXN];
__device__ int     g_incl[MAXN];
__device__ int     g_bsum[512];
__device__ int     g_src[MAXE];
__device__ int     g_dst[MAXE];
__device__ int     g_csr[MAXE];
__device__ int     g_is64;

__device__ __forceinline__ float warp_sum(float v) {
#pragma unroll
    for (int o = 16; o; o >>= 1) v += __shfl_xor_sync(0xFFFFFFFFu, v, o);
    return v;
}

__device__ __forceinline__ float clip_c(float c) {
    return fminf(fmaxf(c, 0.1f), 10.0f);
}

// ---------------------------------------------------------------------------
// Detect edge-index dtype: int64 vs int32 (JAX may silently emit int32).
// ---------------------------------------------------------------------------
__global__ void k_detect(const long long* __restrict__ ei, int E, long long N) {
    if (threadIdx.x != 0 || blockIdx.x != 0) return;
    int n = E < 1024 ? E : 1024;
    int ok64 = 1;
    for (int i = 0; i < n; i++) {
        long long v = ei[i];
        if (v < 0 || v >= N) { ok64 = 0; break; }
    }
    g_is64 = ok64;
}

// ---------------------------------------------------------------------------
// Convert edge index to int32 src/dst (clamped) + in-degree histogram (int).
// ---------------------------------------------------------------------------
__global__ void k_convert(const void* __restrict__ ei, int* __restrict__ src,
                          int* __restrict__ dst, int* __restrict__ deg,
                          int E, int N) {
    int e = blockIdx.x * blockDim.x + threadIdx.x;
    if (e >= E) return;
    long long s, d;
    if (g_is64) {
        const long long* p = (const long long*)ei;
        s = p[e];
        d = p[(size_t)E + e];
    } else {
        const int* p = (const int*)ei;
        s = p[e];
        d = p[(size_t)E + e];
    }
    int si = (int)min(max(s, 0LL), (long long)(N - 1));
    int di = (int)min(max(d, 0LL), (long long)(N - 1));
    src[e] = si;
    dst[e] = di;
    atomicAdd(&deg[di], 1);
}

// ---------------------------------------------------------------------------
// 3-phase prefix scan over deg[] -> rowstart[] (exclusive, rowstart[0]=0)
// ---------------------------------------------------------------------------
__global__ void k_scanA(const int* __restrict__ deg, int* __restrict__ incl,
                        int* __restrict__ bsum, int N) {
    __shared__ int wsum[8];
    int tid = threadIdx.x, lane = tid & 31, warp = tid >> 5;
    int gid = blockIdx.x * 256 + tid;
    int v = (gid < N) ? deg[gid] : 0;
    int x = v;
#pragma unroll
    for (int o = 1; o < 32; o <<= 1) {
        int y = __shfl_up_sync(0xFFFFFFFFu, x, o);
        if (lane >= o) x += y;
    }
    if (lane == 31) wsum[warp] = x;
    __syncthreads();
    if (warp == 0) {
        int s = (lane < 8) ? wsum[lane] : 0;
        int y = s;
#pragma unroll
        for (int o = 1; o < 8; o <<= 1) {
            int z = __shfl_up_sync(0xFFFFFFFFu, y, o);
            if (lane >= o) y += z;
        }
        if (lane < 8) wsum[lane] = y - s;   // exclusive warp offset
    }
    __syncthreads();
    int inclv = x + wsum[warp];
    if (gid < N) incl[gid] = inclv;
    if (tid == 255) bsum[blockIdx.x] = inclv;
}

__global__ void k_scanB(int* __restrict__ bsum, int nb) {
    __shared__ int wsum[8];
    int tid = threadIdx.x, lane = tid & 31, warp = tid >> 5;
    int v = (tid < nb) ? bsum[tid] : 0;
    int x = v;
#pragma unroll
    for (int o = 1; o < 32; o <<= 1) {
        int y = __shfl_up_sync(0xFFFFFFFFu, x, o);
        if (lane >= o) x += y;
    }
    if (lane == 31) wsum[warp] = x;
    __syncthreads();
    if (warp == 0) {
        int s = (lane < 8) ? wsum[lane] : 0;
        int y = s;
#pragma unroll
        for (int o = 1; o < 8; o <<= 1) {
            int z = __shfl_up_sync(0xFFFFFFFFu, y, o);
            if (lane >= o) y += z;
        }
        if (lane < 8) wsum[lane] = y - s;
    }
    __syncthreads();
    if (tid < nb) bsum[tid] = x + wsum[warp] - v;   // exclusive block offset
}

__global__ void k_scanC(const int* __restrict__ incl, const int* __restrict__ bsum,
                        int* __restrict__ rowstart, int N) {
    int gid = blockIdx.x * 256 + threadIdx.x;
    if (gid == 0) rowstart[0] = 0;
    if (gid < N) rowstart[gid + 1] = incl[gid] + bsum[blockIdx.x];
}

__global__ void k_fill(const int* __restrict__ src, const int* __restrict__ dst,
                       const int* __restrict__ rowstart, int* __restrict__ cursor,
                       int* __restrict__ csr, int E) {
    int e = blockIdx.x * blockDim.x + threadIdx.x;
    if (e >= E) return;
    int d = dst[e];
    int pos = rowstart[d] + atomicAdd(&cursor[d], 1);
    csr[pos] = src[e];
}

// ---------------------------------------------------------------------------
// Fused logmap + GEMM: xtan = logmap(x); x_lin = xtan @ W^T + b (fp16 out).
// Tile 32 rows x 128 cols, 256 threads, 4x4 register tile per thread.
// Each warp owns rows r0..r0+3 exclusively -> warp-local logmap, no extra sync.
// Single-buffered W staging (static smem limit), 33.8 KB total.
// ---------------------------------------------------------------------------
__global__ void __launch_bounds__(256) k_gemm_fused(
        const float* __restrict__ xin, const float* __restrict__ W,
        const float* __restrict__ b, float* __restrict__ xtan,
        __half2* __restrict__ xl16, const float* __restrict__ curv,
        int l, int N) {
    __shared__ float xs[32][D];          // 16 KB
    __shared__ float ws[32][136];        // 17.4 KB, ws[kk][j] = W[j][kc*32+kk]
    int tid = threadIdx.x;
    int row0 = blockIdx.x * 32;
    int lane = tid & 31;
    int r0 = (tid >> 5) * 4;             // warp -> 4 rows
    int c0 = lane * 4;                   // lane -> 4 cols

    // load 32 rows of x (1024 float4)
    {
        const float4* srcp = reinterpret_cast<const float4*>(xin + (size_t)row0 * D);
        float4* dstp = reinterpret_cast<float4*>(&xs[0][0]);
        for (int i = tid; i < 1024; i += 256) {
            int r = i >> 5;
            dstp[i] = (row0 + r < N) ? srcp[i] : make_float4(0.f, 0.f, 0.f, 0.f);
        }
    }
    __syncthreads();

    float c = clip_c(curv[l]);
    float K = 1.0f / c;
    float sqrtK = sqrtf(K);

    // logmap rows r0..r0+3 in place (warp-local, each warp owns its rows)
#pragma unroll
    for (int r = 0; r < 4; r++) {
        int row = r0 + r;
        float4 v = *reinterpret_cast<const float4*>(&xs[row][c0]);
        float ss = v.x * v.x + v.y * v.y + v.z * v.z + v.w * v.w;
        ss = warp_sum(ss);
        float xnorm = sqrtf(ss);
        float t = sqrtf(K + ss);
        float theta = acoshf(fmaxf(t / sqrtK, 1.0f + 1e-7f));
        float s = sqrtK * theta / fmaxf(xnorm, 1e-7f);
        v.x *= s; v.y *= s; v.z *= s; v.w *= s;
        *reinterpret_cast<float4*>(&xs[row][c0]) = v;
        int rr = row0 + row;
        if (rr < N)
            *reinterpret_cast<float4*>(&xtan[(size_t)rr * D + c0]) = v;
    }

    float acc[4][4];
#pragma unroll
    for (int r = 0; r < 4; r++)
#pragma unroll
        for (int cc = 0; cc < 4; cc++) acc[r][cc] = 0.0f;

    int js = (tid >> 3);
    int kgs = (tid & 7) * 4;

    for (int kc = 0; kc < 4; kc++) {
        __syncthreads();
        // stage ws[kk][j] = W[j][kc*32+kk]; coalesced global reads
#pragma unroll
        for (int p = 0; p < 4; p++) {
            int j = js + p * 32;
            float4 w4 = *reinterpret_cast<const float4*>(&W[(size_t)j * D + kc * 32 + kgs]);
            ws[kgs + 0][j] = w4.x;
            ws[kgs + 1][j] = w4.y;
            ws[kgs + 2][j] = w4.z;
            ws[kgs + 3][j] = w4.w;
        }
        __syncthreads();
#pragma unroll
        for (int k4 = 0; k4 < 8; k4++) {
            float4 xv[4], wv[4];
#pragma unroll
            for (int r = 0; r < 4; r++)
                xv[r] = *reinterpret_cast<const float4*>(&xs[r0 + r][kc * 32 + k4 * 4]);
#pragma unroll
            for (int q = 0; q < 4; q++)
                wv[q] = *reinterpret_cast<const float4*>(&ws[k4 * 4 + q][c0]);
#pragma unroll
            for (int r = 0; r < 4; r++) {
                const float* xp = reinterpret_cast<const float*>(&xv[r]);
#pragma unroll
                for (int q = 0; q < 4; q++) {
                    acc[r][0] += xp[q] * wv[q].x;
                    acc[r][1] += xp[q] * wv[q].y;
                    acc[r][2] += xp[q] * wv[q].z;
                    acc[r][3] += xp[q] * wv[q].w;
                }
            }
        }
    }

    float4 bb = *reinterpret_cast<const float4*>(&b[c0]);
#pragma unroll
    for (int r = 0; r < 4; r++) {
        int rr = row0 + r0 + r;
        if (rr < N) {
            float2 lo = make_float2(acc[r][0] + bb.x, acc[r][1] + bb.y);
            float2 hi = make_float2(acc[r][2] + bb.z, acc[r][3] + bb.w);
            __half2 h0 = __float22half2_rn(lo);
            __half2 h1 = __float22half2_rn(hi);
            uint2 u;
            u.x = *reinterpret_cast<unsigned*>(&h0);
            u.y = *reinterpret_cast<unsigned*>(&h1);
            *reinterpret_cast<uint2*>(xl16 + (size_t)rr * (D / 2) + (c0 >> 1)) = u;
        }
    }
}

// ---------------------------------------------------------------------------
// Fused CSR aggregation (fp16 gather, fp32 accumulate) + mean + residual +
// LN + expmap. One warp per destination row; 1 LDG.64 per lane per edge.
// ---------------------------------------------------------------------------
__global__ void k_aggfinal(const int* __restrict__ rowstart, const int* __restrict__ csr,
                           const __half2* __restrict__ xl16, const float* __restrict__ xt,
                           const int* __restrict__ deg,
                           const float* __restrict__ gamma, const float* __restrict__ beta,
                           const float* __restrict__ curv, int l,
                           float* __restrict__ out, int N) {
    int w = (blockIdx.x * blockDim.x + threadIdx.x) >> 5;
    int lane = threadIdx.x & 31;
    if (w >= N) return;

    int beg = rowstart[w];
    int end = rowstart[w + 1];
    float4 acc = make_float4(0.f, 0.f, 0.f, 0.f);
    const uint2* xlu = reinterpret_cast<const uint2*>(xl16);   // 1 uint2 = 4 halves

    int e = beg;
    for (; e + 4 <= end; e += 4) {
        int s0 = __ldg(&csr[e + 0]);
        int s1 = __ldg(&csr[e + 1]);
        int s2 = __ldg(&csr[e + 2]);
        int s3 = __ldg(&csr[e + 3]);
        uint2 q0 = __ldg(&xlu[(size_t)s0 * 32 + lane]);
        uint2 q1 = __ldg(&xlu[(size_t)s1 * 32 + lane]);
        uint2 q2 = __ldg(&xlu[(size_t)s2 * 32 + lane]);
        uint2 q3 = __ldg(&xlu[(size_t)s3 * 32 + lane]);
#pragma unroll
        for (int t = 0; t < 4; t++) {
            uint2 q = t == 0 ? q0 : t == 1 ? q1 : t == 2 ? q2 : q3;
            float2 f0 = __half22float2(*reinterpret_cast<__half2*>(&q.x));
            float2 f1 = __half22float2(*reinterpret_cast<__half2*>(&q.y));
            acc.x += f0.x; acc.y += f0.y; acc.z += f1.x; acc.w += f1.y;
        }
    }
    for (; e < end; e++) {
        int s = __ldg(&csr[e]);
        uint2 q = __ldg(&xlu[(size_t)s * 32 + lane]);
        float2 f0 = __half22float2(*reinterpret_cast<__half2*>(&q.x));
        float2 f1 = __half22float2(*reinterpret_cast<__half2*>(&q.y));
        acc.x += f0.x; acc.y += f0.y; acc.z += f1.x; acc.w += f1.y;
    }

    float c = clip_c(curv[l]);
    float K = 1.0f / c;
    float sqrtK = sqrtf(K);
    int dg = deg[w];
    float rcn = 1.0f / (float)(dg > 1 ? dg : 1);

    float4 t = reinterpret_cast<const float4*>(xt + (size_t)w * D)[lane];
    float4 v = make_float4(t.x + acc.x * rcn, t.y + acc.y * rcn,
                           t.z + acc.z * rcn, t.w + acc.w * rcn);

    float s1 = v.x + v.y + v.z + v.w;
    float s2 = v.x * v.x + v.y * v.y + v.z * v.z + v.w * v.w;
    s1 = warp_sum(s1);
    s2 = warp_sum(s2);
    float mean = s1 * (1.0f / D);
    float var = s2 * (1.0f / D) - mean * mean;
    float rstd = rsqrtf(var + 1e-5f);

    float4 g = reinterpret_cast<const float4*>(gamma)[lane];
    float4 bb = reinterpret_cast<const float4*>(beta)[lane];
    float4 y = make_float4((v.x - mean) * rstd * g.x + bb.x,
                           (v.y - mean) * rstd * g.y + bb.y,
                           (v.z - mean) * rstd * g.z + bb.z,
                           (v.w - mean) * rstd * g.w + bb.w);

    float ss = y.x * y.x + y.y * y.y + y.z * y.z + y.w * y.w;
    ss = warp_sum(ss);
    float vnorm = sqrtf(ss);
    float sc = sqrtK * sinhf(vnorm / sqrtK) / fmaxf(vnorm, 1e-7f);

    float4 o = make_float4(y.x * sc, y.y * sc, y.z * sc, y.w * sc);
    reinterpret_cast<float4*>(out + (size_t)w * D)[lane] = o;
}

// ---------------------------------------------------------------------------
extern "C" void kernel_launch(void* const* d_in, const int* in_sizes, int n_in,
                              void* d_out, int out_size) {
    const float* x_hyp      = (const float*)d_in[0];
    const void*  ei         = d_in[1];
    const float* W          = (const float*)d_in[2];
    const float* b          = (const float*)d_in[3];
    const float* gamma      = (const float*)d_in[4];
    const float* beta       = (const float*)d_in[5];
    const float* curv       = (const float*)d_in[6];

    int N = in_sizes[0] / D;
    int E = in_sizes[1] / 2;
    int L = in_sizes[6];

    float *xtan, *xbuf;
    __half2* xl16;
    int *deg, *rowstart, *cursor, *incl, *bsum, *srcp, *dstp, *csr;
    cudaGetSymbolAddress((void**)&xtan, g_xtan);
    cudaGetSymbolAddress((void**)&xbuf, g_x);
    cudaGetSymbolAddress((void**)&xl16, g_xl16);
    cudaGetSymbolAddress((void**)&deg,  g_deg);
    cudaGetSymbolAddress((void**)&rowstart, g_rowstart);
    cudaGetSymbolAddress((void**)&cursor, g_cursor);
    cudaGetSymbolAddress((void**)&incl, g_incl);
    cudaGetSymbolAddress((void**)&bsum, g_bsum);
    cudaGetSymbolAddress((void**)&srcp, g_src);
    cudaGetSymbolAddress((void**)&dstp, g_dst);
    cudaGetSymbolAddress((void**)&csr,  g_csr);

    int nb = (N + 255) / 256;

    // One-time per call: dtype detect, convert + degree, scan, CSR fill.
    cudaMemsetAsync(deg, 0, (size_t)N * sizeof(int));
    cudaMemsetAsync(cursor, 0, (size_t)N * sizeof(int));
    k_detect<<<1, 32>>>((const long long*)ei, E, (long long)N);
    k_convert<<<(E + 255) / 256, 256>>>(ei, srcp, dstp, deg, E, N);
    k_scanA<<<nb, 256>>>(deg, incl, bsum, N);
    k_scanB<<<1, 256>>>(bsum, nb);
    k_scanC<<<nb, 256>>>(incl, bsum, rowstart, N);
    k_fill<<<(E + 255) / 256, 256>>>(srcp, dstp, rowstart, cursor, csr, E);

    int rowBlocks = (N * 32 + 255) / 256;        // warp-per-row kernels

    const float* xin = x_hyp;
    for (int l = 0; l < L; l++) {
        k_gemm_fused<<<(N + 31) / 32, 256>>>(xin, W + (size_t)l * D * D,
                                             b + (size_t)l * D, xtan, xl16,
                                             curv, l, N);
        float* out = (l == L - 1) ? (float*)d_out : xbuf;
        k_aggfinal<<<rowBlocks, 256>>>(rowstart, csr, xl16, xtan, deg,
                                       gamma + (size_t)l * D, beta + (size_t)l * D,
                                       curv, l, out, N);
        xin = xbuf;
    }
}

// round 7
// speedup vs baseline: 2.1489x; 1.1900x over previous
#include <cuda_runtime.h>
#include <cuda_fp16.h>
#include <math.h>

#define D 128
#define MAXN 65536
#define MAXE 1100000

// Scratch (allocation-free rule: __device__ globals)
__device__ float   g_xtan[MAXN * D];
__device__ float   g_x[MAXN * D];
__device__ __half2 g_xl16[MAXN * (D / 2)];
__device__ int     g_deg[MAXN];
__device__ int     g_rowstart[MAXN + 1];
__device__ int     g_cursor[MAXN];
__device__ int     g_incl[MAXN];
__device__ int     g_bsum[512];
__device__ int     g_src[MAXE];
__device__ int     g_dst[MAXE];
__device__ int     g_csr[MAXE];
__device__ int     g_is64;

__device__ __forceinline__ float warp_sum(float v) {
#pragma unroll
    for (int o = 16; o; o >>= 1) v += __shfl_xor_sync(0xFFFFFFFFu, v, o);
    return v;
}

__device__ __forceinline__ float clip_c(float c) {
    return fminf(fmaxf(c, 0.1f), 10.0f);
}

__device__ __forceinline__ unsigned smem_u32(const void* p) {
    return (unsigned)__cvta_generic_to_shared(p);
}

// ---------------------------------------------------------------------------
// Detect edge-index dtype: int64 vs int32 (JAX may silently emit int32).
// ---------------------------------------------------------------------------
__global__ void k_detect(const long long* __restrict__ ei, int E, long long N) {
    if (threadIdx.x != 0 || blockIdx.x != 0) return;
    int n = E < 1024 ? E : 1024;
    int ok64 = 1;
    for (int i = 0; i < n; i++) {
        long long v = ei[i];
        if (v < 0 || v >= N) { ok64 = 0; break; }
    }
    g_is64 = ok64;
}

// ---------------------------------------------------------------------------
// Convert edge index to int32 src/dst (clamped) + in-degree histogram (int).
// ---------------------------------------------------------------------------
__global__ void k_convert(const void* __restrict__ ei, int* __restrict__ src,
                          int* __restrict__ dst, int* __restrict__ deg,
                          int E, int N) {
    int e = blockIdx.x * blockDim.x + threadIdx.x;
    if (e >= E) return;
    long long s, d;
    if (g_is64) {
        const long long* p = (const long long*)ei;
        s = p[e];
        d = p[(size_t)E + e];
    } else {
        const int* p = (const int*)ei;
        s = p[e];
        d = p[(size_t)E + e];
    }
    int si = (int)min(max(s, 0LL), (long long)(N - 1));
    int di = (int)min(max(d, 0LL), (long long)(N - 1));
    src[e] = si;
    dst[e] = di;
    atomicAdd(&deg[di], 1);
}

// ---------------------------------------------------------------------------
// 3-phase prefix scan over deg[] -> rowstart[] (exclusive, rowstart[0]=0)
// ---------------------------------------------------------------------------
__global__ void k_scanA(const int* __restrict__ deg, int* __restrict__ incl,
                        int* __restrict__ bsum, int N) {
    __shared__ int wsum[8];
    int tid = threadIdx.x, lane = tid & 31, warp = tid >> 5;
    int gid = blockIdx.x * 256 + tid;
    int v = (gid < N) ? deg[gid] : 0;
    int x = v;
#pragma unroll
    for (int o = 1; o < 32; o <<= 1) {
        int y = __shfl_up_sync(0xFFFFFFFFu, x, o);
        if (lane >= o) x += y;
    }
    if (lane == 31) wsum[warp] = x;
    __syncthreads();
    if (warp == 0) {
        int s = (lane < 8) ? wsum[lane] : 0;
        int y = s;
#pragma unroll
        for (int o = 1; o < 8; o <<= 1) {
            int z = __shfl_up_sync(0xFFFFFFFFu, y, o);
            if (lane >= o) y += z;
        }
        if (lane < 8) wsum[lane] = y - s;   // exclusive warp offset
    }
    __syncthreads();
    int inclv = x + wsum[warp];
    if (gid < N) incl[gid] = inclv;
    if (tid == 255) bsum[blockIdx.x] = inclv;
}

__global__ void k_scanB(int* __restrict__ bsum, int nb) {
    __shared__ int wsum[8];
    int tid = threadIdx.x, lane = tid & 31, warp = tid >> 5;
    int v = (tid < nb) ? bsum[tid] : 0;
    int x = v;
#pragma unroll
    for (int o = 1; o < 32; o <<= 1) {
        int y = __shfl_up_sync(0xFFFFFFFFu, x, o);
        if (lane >= o) x += y;
    }
    if (lane == 31) wsum[warp] = x;
    __syncthreads();
    if (warp == 0) {
        int s = (lane < 8) ? wsum[lane] : 0;
        int y = s;
#pragma unroll
        for (int o = 1; o < 8; o <<= 1) {
            int z = __shfl_up_sync(0xFFFFFFFFu, y, o);
            if (lane >= o) y += z;
        }
        if (lane < 8) wsum[lane] = y - s;
    }
    __syncthreads();
    if (tid < nb) bsum[tid] = x + wsum[warp] - v;   // exclusive block offset
}

__global__ void k_scanC(const int* __restrict__ incl, const int* __restrict__ bsum,
                        int* __restrict__ rowstart, int N) {
    int gid = blockIdx.x * 256 + threadIdx.x;
    if (gid == 0) rowstart[0] = 0;
    if (gid < N) rowstart[gid + 1] = incl[gid] + bsum[blockIdx.x];
}

__global__ void k_fill(const int* __restrict__ src, const int* __restrict__ dst,
                       const int* __restrict__ rowstart, int* __restrict__ cursor,
                       int* __restrict__ csr, int E) {
    int e = blockIdx.x * blockDim.x + threadIdx.x;
    if (e >= E) return;
    int d = dst[e];
    int pos = rowstart[d] + atomicAdd(&cursor[d], 1);
    csr[pos] = src[e];
}

// ---------------------------------------------------------------------------
// Fused logmap + HMMA GEMM: xtan = logmap(x); x_lin = xtan @ W^T + b (fp16).
// Block: 128 rows x 128 cols, 8 warps; warp w owns rows w*16..w*16+15.
// A (fp16 xtan) in smem pitch 136 halves (272B, conflict-free ldmatrix).
// W staged per k=32 chunk, fp16, pitch 48 halves (96B, 16B-aligned, c-free).
// mma.sync.m16n8k16 f16*f16+f32; 16 n-tiles x 4 f32 accumulators per thread.
// ---------------------------------------------------------------------------
__global__ void __launch_bounds__(256) k_gemm_fused(
        const float* __restrict__ xin, const float* __restrict__ W,
        const float* __restrict__ b, float* __restrict__ xtan,
        __half2* __restrict__ xl16, const float* __restrict__ curv,
        int l, int N) {
    __shared__ __half As[128][136];   // 34816 B
    __shared__ __half Bs[128][48];    // 12288 B  (total 46 KB)
    int tid = threadIdx.x;
    int lane = tid & 31;
    int wid = tid >> 5;
    int row0 = blockIdx.x * 128;
    int m0 = wid * 16;

    float c = clip_c(curv[l]);
    float K = 1.0f / c;
    float sqrtK = sqrtf(K);

    // Stage 1: load x rows, logmap, write xtan (fp32) + As (fp16).
    // Warp w handles rows m0..m0+15.
#pragma unroll
    for (int i = 0; i < 16; i++) {
        int row = m0 + i;
        int grow = row0 + row;
        float4 v = make_float4(0.f, 0.f, 0.f, 0.f);
        if (grow < N)
            v = __ldg(reinterpret_cast<const float4*>(xin + (size_t)grow * D) + lane);
        float ss = v.x * v.x + v.y * v.y + v.z * v.z + v.w * v.w;
        ss = warp_sum(ss);
        float xnorm = sqrtf(ss);
        float t = sqrtf(K + ss);
        float theta = acoshf(fmaxf(t / sqrtK, 1.0f + 1e-7f));
        float s = sqrtK * theta / fmaxf(xnorm, 1e-7f);
        v.x *= s; v.y *= s; v.z *= s; v.w *= s;
        if (grow < N)
            *reinterpret_cast<float4*>(&xtan[(size_t)grow * D + lane * 4]) = v;
        __half2 h0 = __float22half2_rn(make_float2(v.x, v.y));
        __half2 h1 = __float22half2_rn(make_float2(v.z, v.w));
        uint2 u;
        u.x = *reinterpret_cast<unsigned*>(&h0);
        u.y = *reinterpret_cast<unsigned*>(&h1);
        *reinterpret_cast<uint2*>(&As[row][lane * 4]) = u;
    }

    float acc[16][4];
#pragma unroll
    for (int nt = 0; nt < 16; nt++)
#pragma unroll
        for (int q = 0; q < 4; q++) acc[nt][q] = 0.0f;

    // ldmatrix lane address components
    int a_rr = lane & 7;
    int a_sel = lane >> 3;                  // 0..3
    int a_row = m0 + a_rr + ((a_sel & 1) ? 8 : 0);
    int a_koff = (a_sel >> 1) ? 8 : 0;
    int b_rr = lane & 7;
    int b_koff = ((lane >> 3) & 1) ? 8 : 0;

    // W staging assignment: thread -> row j, k-half
    int wj = tid >> 1;
    int wkh = (tid & 1) * 16;

    for (int kc = 0; kc < 4; kc++) {
        __syncthreads();   // Bs reuse barrier (also covers As visibility, iter 0)
        // stage W chunk: Bs[j][kk] = (half)W[j][kc*32+kk]
        {
            const float4* wp = reinterpret_cast<const float4*>(
                &W[(size_t)wj * D + kc * 32 + wkh]);
            float4 w0 = __ldg(wp + 0);
            float4 w1 = __ldg(wp + 1);
            float4 w2 = __ldg(wp + 2);
            float4 w3 = __ldg(wp + 3);
            __half2 h0 = __float22half2_rn(make_float2(w0.x, w0.y));
            __half2 h1 = __float22half2_rn(make_float2(w0.z, w0.w));
            __half2 h2 = __float22half2_rn(make_float2(w1.x, w1.y));
            __half2 h3 = __float22half2_rn(make_float2(w1.z, w1.w));
            __half2 h4 = __float22half2_rn(make_float2(w2.x, w2.y));
            __half2 h5 = __float22half2_rn(make_float2(w2.z, w2.w));
            __half2 h6 = __float22half2_rn(make_float2(w3.x, w3.y));
            __half2 h7 = __float22half2_rn(make_float2(w3.z, w3.w));
            uint4 u0, u1;
            u0.x = *reinterpret_cast<unsigned*>(&h0);
            u0.y = *reinterpret_cast<unsigned*>(&h1);
            u0.z = *reinterpret_cast<unsigned*>(&h2);
            u0.w = *reinterpret_cast<unsigned*>(&h3);
            u1.x = *reinterpret_cast<unsigned*>(&h4);
            u1.y = *reinterpret_cast<unsigned*>(&h5);
            u1.z = *reinterpret_cast<unsigned*>(&h6);
            u1.w = *reinterpret_cast<unsigned*>(&h7);
            *reinterpret_cast<uint4*>(&Bs[wj][wkh + 0]) = u0;
            *reinterpret_cast<uint4*>(&Bs[wj][wkh + 8]) = u1;
        }
        __syncthreads();

#pragma unroll
        for (int s = 0; s < 2; s++) {
            int kg = kc * 32 + s * 16;      // global k for A
            int ks = s * 16;                // chunk-local k for B
            unsigned a0, a1, a2, a3;
            unsigned aaddr = smem_u32(&As[a_row][kg + a_koff]);
            asm volatile(
                "ldmatrix.sync.aligned.m8n8.x4.shared.b16 {%0,%1,%2,%3}, [%4];"
                : "=r"(a0), "=r"(a1), "=r"(a2), "=r"(a3) : "r"(aaddr));
#pragma unroll
            for (int nt = 0; nt < 16; nt++) {
                unsigned b0, b1;
                unsigned baddr = smem_u32(&Bs[nt * 8 + b_rr][ks + b_koff]);
                asm volatile(
                    "ldmatrix.sync.aligned.m8n8.x2.shared.b16 {%0,%1}, [%2];"
                    : "=r"(b0), "=r"(b1) : "r"(baddr));
                asm volatile(
                    "mma.sync.aligned.m16n8k16.row.col.f32.f16.f16.f32 "
                    "{%0,%1,%2,%3}, {%4,%5,%6,%7}, {%8,%9}, {%0,%1,%2,%3};"
                    : "+f"(acc[nt][0]), "+f"(acc[nt][1]),
                      "+f"(acc[nt][2]), "+f"(acc[nt][3])
                    : "r"(a0), "r"(a1), "r"(a2), "r"(a3), "r"(b0), "r"(b1));
            }
        }
    }

    // Epilogue: add bias, convert to fp16, store xl16.
    int gid = lane >> 2;     // C-fragment row group
    int tig = lane & 3;      // C-fragment col pair
    int row1 = row0 + m0 + gid;
    int row2 = row1 + 8;
#pragma unroll
    for (int nt = 0; nt < 16; nt++) {
        int col = nt * 8 + 2 * tig;
        float2 bv = *reinterpret_cast<const float2*>(&b[col]);
        if (row1 < N) {
            __half2 h = __float22half2_rn(
                make_float2(acc[nt][0] + bv.x, acc[nt][1] + bv.y));
            xl16[(size_t)row1 * (D / 2) + (col >> 1)] = h;
        }
        if (row2 < N) {
            __half2 h = __float22half2_rn(
                make_float2(acc[nt][2] + bv.x, acc[nt][3] + bv.y));
            xl16[(size_t)row2 * (D / 2) + (col >> 1)] = h;
        }
    }
}

// ---------------------------------------------------------------------------
// Fused CSR aggregation (fp16 gather, fp32 accumulate) + mean + residual +
// LN + expmap. One warp per destination row; 1 LDG.64 per lane per edge.
// ---------------------------------------------------------------------------
__global__ void k_aggfinal(const int* __restrict__ rowstart, const int* __restrict__ csr,
                           const __half2* __restrict__ xl16, const float* __restrict__ xt,
                           const int* __restrict__ deg,
                           const float* __restrict__ gamma, const float* __restrict__ beta,
                           const float* __restrict__ curv, int l,
                           float* __restrict__ out, int N) {
    int w = (blockIdx.x * blockDim.x + threadIdx.x) >> 5;
    int lane = threadIdx.x & 31;
    if (w >= N) return;

    int beg = rowstart[w];
    int end = rowstart[w + 1];
    float4 acc = make_float4(0.f, 0.f, 0.f, 0.f);
    const uint2* xlu = reinterpret_cast<const uint2*>(xl16);   // 1 uint2 = 4 halves

    int e = beg;
    for (; e + 4 <= end; e += 4) {
        int s0 = __ldg(&csr[e + 0]);
        int s1 = __ldg(&csr[e + 1]);
        int s2 = __ldg(&csr[e + 2]);
        int s3 = __ldg(&csr[e + 3]);
        uint2 q0 = __ldg(&xlu[(size_t)s0 * 32 + lane]);
        uint2 q1 = __ldg(&xlu[(size_t)s1 * 32 + lane]);
        uint2 q2 = __ldg(&xlu[(size_t)s2 * 32 + lane]);
        uint2 q3 = __ldg(&xlu[(size_t)s3 * 32 + lane]);
#pragma unroll
        for (int t = 0; t < 4; t++) {
            uint2 q = t == 0 ? q0 : t == 1 ? q1 : t == 2 ? q2 : q3;
            float2 f0 = __half22float2(*reinterpret_cast<__half2*>(&q.x));
            float2 f1 = __half22float2(*reinterpret_cast<__half2*>(&q.y));
            acc.x += f0.x; acc.y += f0.y; acc.z += f1.x; acc.w += f1.y;
        }
    }
    for (; e < end; e++) {
        int s = __ldg(&csr[e]);
        uint2 q = __ldg(&xlu[(size_t)s * 32 + lane]);
        float2 f0 = __half22float2(*reinterpret_cast<__half2*>(&q.x));
        float2 f1 = __half22float2(*reinterpret_cast<__half2*>(&q.y));
        acc.x += f0.x; acc.y += f0.y; acc.z += f1.x; acc.w += f1.y;
    }

    float c = clip_c(curv[l]);
    float K = 1.0f / c;
    float sqrtK = sqrtf(K);
    int dg = deg[w];
    float rcn = 1.0f / (float)(dg > 1 ? dg : 1);

    float4 t = reinterpret_cast<const float4*>(xt + (size_t)w * D)[lane];
    float4 v = make_float4(t.x + acc.x * rcn, t.y + acc.y * rcn,
                           t.z + acc.z * rcn, t.w + acc.w * rcn);

    float s1 = v.x + v.y + v.z + v.w;
    float s2 = v.x * v.x + v.y * v.y + v.z * v.z + v.w * v.w;
    s1 = warp_sum(s1);
    s2 = warp_sum(s2);
    float mean = s1 * (1.0f / D);
    float var = s2 * (1.0f / D) - mean * mean;
    float rstd = rsqrtf(var + 1e-5f);

    float4 g = reinterpret_cast<const float4*>(gamma)[lane];
    float4 bb = reinterpret_cast<const float4*>(beta)[lane];
    float4 y = make_float4((v.x - mean) * rstd * g.x + bb.x,
                           (v.y - mean) * rstd * g.y + bb.y,
                           (v.z - mean) * rstd * g.z + bb.z,
                           (v.w - mean) * rstd * g.w + bb.w);

    float ss = y.x * y.x + y.y * y.y + y.z * y.z + y.w * y.w;
    ss = warp_sum(ss);
    float vnorm = sqrtf(ss);
    float sc = sqrtK * sinhf(vnorm / sqrtK) / fmaxf(vnorm, 1e-7f);

    float4 o = make_float4(y.x * sc, y.y * sc, y.z * sc, y.w * sc);
    reinterpret_cast<float4*>(out + (size_t)w * D)[lane] = o;
}

// ---------------------------------------------------------------------------
extern "C" void kernel_launch(void* const* d_in, const int* in_sizes, int n_in,
                              void* d_out, int out_size) {
    const float* x_hyp      = (const float*)d_in[0];
    const void*  ei         = d_in[1];
    const float* W          = (const float*)d_in[2];
    const float* b          = (const float*)d_in[3];
    const float* gamma      = (const float*)d_in[4];
    const float* beta       = (const float*)d_in[5];
    const float* curv       = (const float*)d_in[6];

    int N = in_sizes[0] / D;
    int E = in_sizes[1] / 2;
    int L = in_sizes[6];

    float *xtan, *xbuf;
    __half2* xl16;
    int *deg, *rowstart, *cursor, *incl, *bsum, *srcp, *dstp, *csr;
    cudaGetSymbolAddress((void**)&xtan, g_xtan);
    cudaGetSymbolAddress((void**)&xbuf, g_x);
    cudaGetSymbolAddress((void**)&xl16, g_xl16);
    cudaGetSymbolAddress((void**)&deg,  g_deg);
    cudaGetSymbolAddress((void**)&rowstart, g_rowstart);
    cudaGetSymbolAddress((void**)&cursor, g_cursor);
    cudaGetSymbolAddress((void**)&incl, g_incl);
    cudaGetSymbolAddress((void**)&bsum, g_bsum);
    cudaGetSymbolAddress((void**)&srcp, g_src);
    cudaGetSymbolAddress((void**)&dstp, g_dst);
    cudaGetSymbolAddress((void**)&csr,  g_csr);

    int nb = (N + 255) / 256;

    // One-time per call: dtype detect, convert + degree, scan, CSR fill.
    cudaMemsetAsync(deg, 0, (size_t)N * sizeof(int));
    cudaMemsetAsync(cursor, 0, (size_t)N * sizeof(int));
    k_detect<<<1, 32>>>((const long long*)ei, E, (long long)N);
    k_convert<<<(E + 255) / 256, 256>>>(ei, srcp, dstp, deg, E, N);
    k_scanA<<<nb, 256>>>(deg, incl, bsum, N);
    k_scanB<<<1, 256>>>(bsum, nb);
    k_scanC<<<nb, 256>>>(incl, bsum, rowstart, N);
    k_fill<<<(E + 255) / 256, 256>>>(srcp, dstp, rowstart, cursor, csr, E);

    int rowBlocks = (N * 32 + 255) / 256;        // warp-per-row kernels

    const float* xin = x_hyp;
    for (int l = 0; l < L; l++) {
        k_gemm_fused<<<(N + 127) / 128, 256>>>(xin, W + (size_t)l * D * D,
                                               b + (size_t)l * D, xtan, xl16,
                                               curv, l, N);
        float* out = (l == L - 1) ? (float*)d_out : xbuf;
        k_aggfinal<<<rowBlocks, 256>>>(rowstart, csr, xl16, xtan, deg,
                                       gamma + (size_t)l * D, beta + (size_t)l * D,
                                       curv, l, out, N);
        xin = xbuf;
    }
}

// round 8
// speedup vs baseline: 2.1492x; 1.0002x over previous
#include <cuda_runtime.h>
#include <cuda_fp16.h>
#include <math.h>

#define D 128
#define MAXN 65536
#define MAXE 1100000

// Scratch (allocation-free rule: __device__ globals)
__device__ float   g_xtan[MAXN * D];
__device__ float   g_x[MAXN * D];
__device__ __half2 g_xl16[MAXN * (D / 2)];
__device__ int     g_deg[MAXN];
__device__ int     g_rowstart[MAXN + 1];
__device__ int     g_cursor[MAXN];
__device__ int     g_incl[MAXN];
__device__ int     g_bsum[512];
__device__ int     g_csr[MAXE];
__device__ int     g_is64;

__device__ __forceinline__ float warp_sum(float v) {
#pragma unroll
    for (int o = 16; o; o >>= 1) v += __shfl_xor_sync(0xFFFFFFFFu, v, o);
    return v;
}

__device__ __forceinline__ float clip_c(float c) {
    return fminf(fmaxf(c, 0.1f), 10.0f);
}

__device__ __forceinline__ unsigned smem_u32(const void* p) {
    return (unsigned)__cvta_generic_to_shared(p);
}

// ---------------------------------------------------------------------------
// Detect edge-index dtype: int64 vs int32. Parallel (256 threads + ballot);
// the old single-thread version was a serial dependent-load chain (~25us).
// ---------------------------------------------------------------------------
__global__ void k_detect(const long long* __restrict__ ei, int E, long long N) {
    int tid = threadIdx.x;
    int n = E < 1024 ? E : 1024;
    int bad = 0;
    for (int i = tid; i < n; i += 256) {
        long long v = ei[i];
        if (v < 0 || v >= N) bad = 1;
    }
    int any = __syncthreads_or(bad);
    if (tid == 0) g_is64 = !any;
}

// ---------------------------------------------------------------------------
// In-degree histogram straight from ei (dtype-branched).
// ---------------------------------------------------------------------------
__global__ void k_hist(const void* __restrict__ ei, int* __restrict__ deg,
                       int E, int N) {
    int e = blockIdx.x * blockDim.x + threadIdx.x;
    if (e >= E) return;
    long long d;
    if (g_is64) d = ((const long long*)ei)[(size_t)E + e];
    else        d = ((const int*)ei)[(size_t)E + e];
    int di = (int)min(max(d, 0LL), (long long)(N - 1));
    atomicAdd(&deg[di], 1);
}

// ---------------------------------------------------------------------------
// 3-phase prefix scan over deg[] -> rowstart[] (exclusive, rowstart[0]=0)
// ---------------------------------------------------------------------------
__global__ void k_scanA(const int* __restrict__ deg, int* __restrict__ incl,
                        int* __restrict__ bsum, int N) {
    __shared__ int wsum[8];
    int tid = threadIdx.x, lane = tid & 31, warp = tid >> 5;
    int gid = blockIdx.x * 256 + tid;
    int v = (gid < N) ? deg[gid] : 0;
    int x = v;
#pragma unroll
    for (int o = 1; o < 32; o <<= 1) {
        int y = __shfl_up_sync(0xFFFFFFFFu, x, o);
        if (lane >= o) x += y;
    }
    if (lane == 31) wsum[warp] = x;
    __syncthreads();
    if (warp == 0) {
        int s = (lane < 8) ? wsum[lane] : 0;
        int y = s;
#pragma unroll
        for (int o = 1; o < 8; o <<= 1) {
            int z = __shfl_up_sync(0xFFFFFFFFu, y, o);
            if (lane >= o) y += z;
        }
        if (lane < 8) wsum[lane] = y - s;   // exclusive warp offset
    }
    __syncthreads();
    int inclv = x + wsum[warp];
    if (gid < N) incl[gid] = inclv;
    if (tid == 255) bsum[blockIdx.x] = inclv;
}

__global__ void k_scanB(int* __restrict__ bsum, int nb) {
    __shared__ int wsum[8];
    int tid = threadIdx.x, lane = tid & 31, warp = tid >> 5;
    int v = (tid < nb) ? bsum[tid] : 0;
    int x = v;
#pragma unroll
    for (int o = 1; o < 32; o <<= 1) {
        int y = __shfl_up_sync(0xFFFFFFFFu, x, o);
        if (lane >= o) x += y;
    }
    if (lane == 31) wsum[warp] = x;
    __syncthreads();
    if (warp == 0) {
        int s = (lane < 8) ? wsum[lane] : 0;
        int y = s;
#pragma unroll
        for (int o = 1; o < 8; o <<= 1) {
            int z = __shfl_up_sync(0xFFFFFFFFu, y, o);
            if (lane >= o) y += z;
        }
        if (lane < 8) wsum[lane] = y - s;
    }
    __syncthreads();
    if (tid < nb) bsum[tid] = x + wsum[warp] - v;   // exclusive block offset
}

__global__ void k_scanC(const int* __restrict__ incl, const int* __restrict__ bsum,
                        int* __restrict__ rowstart, int N) {
    int gid = blockIdx.x * 256 + threadIdx.x;
    if (gid == 0) rowstart[0] = 0;
    if (gid < N) rowstart[gid + 1] = incl[gid] + bsum[blockIdx.x];
}

// ---------------------------------------------------------------------------
// CSR fill straight from ei (dtype-branched, clamped).
// ---------------------------------------------------------------------------
__global__ void k_fill(const void* __restrict__ ei,
                       const int* __restrict__ rowstart, int* __restrict__ cursor,
                       int* __restrict__ csr, int E, int N) {
    int e = blockIdx.x * blockDim.x + threadIdx.x;
    if (e >= E) return;
    long long s, d;
    if (g_is64) {
        const long long* p = (const long long*)ei;
        s = p[e];
        d = p[(size_t)E + e];
    } else {
        const int* p = (const int*)ei;
        s = p[e];
        d = p[(size_t)E + e];
    }
    int si = (int)min(max(s, 0LL), (long long)(N - 1));
    int di = (int)min(max(d, 0LL), (long long)(N - 1));
    int pos = rowstart[di] + atomicAdd(&cursor[di], 1);
    csr[pos] = si;
}

// ---------------------------------------------------------------------------
// Fused logmap + HMMA GEMM: xtan = logmap(x); x_lin = xtan @ W^T + b (fp16).
// Block: 128 rows x 128 cols, 8 warps; warp w owns rows w*16..w*16+15.
// mma.sync.m16n8k16 f16*f16+f32; 16 n-tiles x 4 f32 accumulators per thread.
// ---------------------------------------------------------------------------
__global__ void __launch_bounds__(256) k_gemm_fused(
        const float* __restrict__ xin, const float* __restrict__ W,
        const float* __restrict__ b, float* __restrict__ xtan,
        __half2* __restrict__ xl16, const float* __restrict__ curv,
        int l, int N) {
    __shared__ __half As[128][136];   // 34816 B
    __shared__ __half Bs[128][48];    // 12288 B  (total 46 KB)
    int tid = threadIdx.x;
    int lane = tid & 31;
    int wid = tid >> 5;
    int row0 = blockIdx.x * 128;
    int m0 = wid * 16;

    float c = clip_c(curv[l]);
    float K = 1.0f / c;
    float sqrtK = sqrtf(K);

    // Stage 1: load x rows, logmap, write xtan (fp32) + As (fp16).
#pragma unroll
    for (int i = 0; i < 16; i++) {
        int row = m0 + i;
        int grow = row0 + row;
        float4 v = make_float4(0.f, 0.f, 0.f, 0.f);
        if (grow < N)
            v = __ldg(reinterpret_cast<const float4*>(xin + (size_t)grow * D) + lane);
        float ss = v.x * v.x + v.y * v.y + v.z * v.z + v.w * v.w;
        ss = warp_sum(ss);
        float xnorm = sqrtf(ss);
        float t = sqrtf(K + ss);
        float theta = acoshf(fmaxf(t / sqrtK, 1.0f + 1e-7f));
        float s = sqrtK * theta / fmaxf(xnorm, 1e-7f);
        v.x *= s; v.y *= s; v.z *= s; v.w *= s;
        if (grow < N)
            *reinterpret_cast<float4*>(&xtan[(size_t)grow * D + lane * 4]) = v;
        __half2 h0 = __float22half2_rn(make_float2(v.x, v.y));
        __half2 h1 = __float22half2_rn(make_float2(v.z, v.w));
        uint2 u;
        u.x = *reinterpret_cast<unsigned*>(&h0);
        u.y = *reinterpret_cast<unsigned*>(&h1);
        *reinterpret_cast<uint2*>(&As[row][lane * 4]) = u;
    }

    float acc[16][4];
#pragma unroll
    for (int nt = 0; nt < 16; nt++)
#pragma unroll
        for (int q = 0; q < 4; q++) acc[nt][q] = 0.0f;

    // ldmatrix lane address components
    int a_rr = lane & 7;
    int a_sel = lane >> 3;                  // 0..3
    int a_row = m0 + a_rr + ((a_sel & 1) ? 8 : 0);
    int a_koff = (a_sel >> 1) ? 8 : 0;
    int b_rr = lane & 7;
    int b_koff = ((lane >> 3) & 1) ? 8 : 0;

    // W staging assignment: thread -> row j, k-half
    int wj = tid >> 1;
    int wkh = (tid & 1) * 16;

    for (int kc = 0; kc < 4; kc++) {
        __syncthreads();   // Bs reuse barrier (also covers As visibility, iter 0)
        // stage W chunk: Bs[j][kk] = (half)W[j][kc*32+kk]
        {
            const float4* wp = reinterpret_cast<const float4*>(
                &W[(size_t)wj * D + kc * 32 + wkh]);
            float4 w0 = __ldg(wp + 0);
            float4 w1 = __ldg(wp + 1);
            float4 w2 = __ldg(wp + 2);
            float4 w3 = __ldg(wp + 3);
            __half2 h0 = __float22half2_rn(make_float2(w0.x, w0.y));
            __half2 h1 = __float22half2_rn(make_float2(w0.z, w0.w));
            __half2 h2 = __float22half2_rn(make_float2(w1.x, w1.y));
            __half2 h3 = __float22half2_rn(make_float2(w1.z, w1.w));
            __half2 h4 = __float22half2_rn(make_float2(w2.x, w2.y));
            __half2 h5 = __float22half2_rn(make_float2(w2.z, w2.w));
            __half2 h6 = __float22half2_rn(make_float2(w3.x, w3.y));
            __half2 h7 = __float22half2_rn(make_float2(w3.z, w3.w));
            uint4 u0, u1;
            u0.x = *reinterpret_cast<unsigned*>(&h0);
            u0.y = *reinterpret_cast<unsigned*>(&h1);
            u0.z = *reinterpret_cast<unsigned*>(&h2);
            u0.w = *reinterpret_cast<unsigned*>(&h3);
            u1.x = *reinterpret_cast<unsigned*>(&h4);
            u1.y = *reinterpret_cast<unsigned*>(&h5);
            u1.z = *reinterpret_cast<unsigned*>(&h6);
            u1.w = *reinterpret_cast<unsigned*>(&h7);
            *reinterpret_cast<uint4*>(&Bs[wj][wkh + 0]) = u0;
            *reinterpret_cast<uint4*>(&Bs[wj][wkh + 8]) = u1;
        }
        __syncthreads();

#pragma unroll
        for (int s = 0; s < 2; s++) {
            int kg = kc * 32 + s * 16;      // global k for A
            int ks = s * 16;                // chunk-local k for B
            unsigned a0, a1, a2, a3;
            unsigned aaddr = smem_u32(&As[a_row][kg + a_koff]);
            asm volatile(
                "ldmatrix.sync.aligned.m8n8.x4.shared.b16 {%0,%1,%2,%3}, [%4];"
                : "=r"(a0), "=r"(a1), "=r"(a2), "=r"(a3) : "r"(aaddr));
#pragma unroll
            for (int nt = 0; nt < 16; nt++) {
                unsigned b0, b1;
                unsigned baddr = smem_u32(&Bs[nt * 8 + b_rr][ks + b_koff]);
                asm volatile(
                    "ldmatrix.sync.aligned.m8n8.x2.shared.b16 {%0,%1}, [%2];"
                    : "=r"(b0), "=r"(b1) : "r"(baddr));
                asm volatile(
                    "mma.sync.aligned.m16n8k16.row.col.f32.f16.f16.f32 "
                    "{%0,%1,%2,%3}, {%4,%5,%6,%7}, {%8,%9}, {%0,%1,%2,%3};"
                    : "+f"(acc[nt][0]), "+f"(acc[nt][1]),
                      "+f"(acc[nt][2]), "+f"(acc[nt][3])
                    : "r"(a0), "r"(a1), "r"(a2), "r"(a3), "r"(b0), "r"(b1));
            }
        }
    }

    // Epilogue: add bias, convert to fp16, store xl16.
    int gid = lane >> 2;     // C-fragment row group
    int tig = lane & 3;      // C-fragment col pair
    int row1 = row0 + m0 + gid;
    int row2 = row1 + 8;
#pragma unroll
    for (int nt = 0; nt < 16; nt++) {
        int col = nt * 8 + 2 * tig;
        float2 bv = *reinterpret_cast<const float2*>(&b[col]);
        if (row1 < N) {
            __half2 h = __float22half2_rn(
                make_float2(acc[nt][0] + bv.x, acc[nt][1] + bv.y));
            xl16[(size_t)row1 * (D / 2) + (col >> 1)] = h;
        }
        if (row2 < N) {
            __half2 h = __float22half2_rn(
                make_float2(acc[nt][2] + bv.x, acc[nt][3] + bv.y));
            xl16[(size_t)row2 * (D / 2) + (col >> 1)] = h;
        }
    }
}

// ---------------------------------------------------------------------------
// Fused CSR aggregation (fp16 gather, fp32 accumulate) + mean + residual +
// LN + expmap. One warp per destination row; unroll-8 for MLP (L2 latency
// hiding), indices prefetched (uniform broadcast loads).
// ---------------------------------------------------------------------------
__global__ void k_aggfinal(const int* __restrict__ rowstart, const int* __restrict__ csr,
                           const __half2* __restrict__ xl16, const float* __restrict__ xt,
                           const int* __restrict__ deg,
                           const float* __restrict__ gamma, const float* __restrict__ beta,
                           const float* __restrict__ curv, int l,
                           float* __restrict__ out, int N) {
    int w = (blockIdx.x * blockDim.x + threadIdx.x) >> 5;
    int lane = threadIdx.x & 31;
    if (w >= N) return;

    int beg = rowstart[w];
    int end = rowstart[w + 1];
    float4 acc = make_float4(0.f, 0.f, 0.f, 0.f);
    const uint2* xlu = reinterpret_cast<const uint2*>(xl16);   // 1 uint2 = 4 halves

    int e = beg;
    for (; e + 8 <= end; e += 8) {
        int sidx[8];
#pragma unroll
        for (int t = 0; t < 8; t++) sidx[t] = __ldg(&csr[e + t]);
        uint2 q[8];
#pragma unroll
        for (int t = 0; t < 8; t++)
            q[t] = __ldg(&xlu[(size_t)sidx[t] * 32 + lane]);
#pragma unroll
        for (int t = 0; t < 8; t++) {
            float2 f0 = __half22float2(*reinterpret_cast<__half2*>(&q[t].x));
            float2 f1 = __half22float2(*reinterpret_cast<__half2*>(&q[t].y));
            acc.x += f0.x; acc.y += f0.y; acc.z += f1.x; acc.w += f1.y;
        }
    }
    if (e + 4 <= end) {
        int sidx[4];
#pragma unroll
        for (int t = 0; t < 4; t++) sidx[t] = __ldg(&csr[e + t]);
        uint2 q[4];
#pragma unroll
        for (int t = 0; t < 4; t++)
            q[t] = __ldg(&xlu[(size_t)sidx[t] * 32 + lane]);
#pragma unroll
        for (int t = 0; t < 4; t++) {
            float2 f0 = __half22float2(*reinterpret_cast<__half2*>(&q[t].x));
            float2 f1 = __half22float2(*reinterpret_cast<__half2*>(&q[t].y));
            acc.x += f0.x; acc.y += f0.y; acc.z += f1.x; acc.w += f1.y;
        }
        e += 4;
    }
    for (; e < end; e++) {
        int s = __ldg(&csr[e]);
        uint2 q = __ldg(&xlu[(size_t)s * 32 + lane]);
        float2 f0 = __half22float2(*reinterpret_cast<__half2*>(&q.x));
        float2 f1 = __half22float2(*reinterpret_cast<__half2*>(&q.y));
        acc.x += f0.x; acc.y += f0.y; acc.z += f1.x; acc.w += f1.y;
    }

    float c = clip_c(curv[l]);
    float K = 1.0f / c;
    float sqrtK = sqrtf(K);
    int dg = deg[w];
    float rcn = 1.0f / (float)(dg > 1 ? dg : 1);

    float4 t = reinterpret_cast<const float4*>(xt + (size_t)w * D)[lane];
    float4 v = make_float4(t.x + acc.x * rcn, t.y + acc.y * rcn,
                           t.z + acc.z * rcn, t.w + acc.w * rcn);

    float s1 = v.x + v.y + v.z + v.w;
    float s2 = v.x * v.x + v.y * v.y + v.z * v.z + v.w * v.w;
    s1 = warp_sum(s1);
    s2 = warp_sum(s2);
    float mean = s1 * (1.0f / D);
    float var = s2 * (1.0f / D) - mean * mean;
    float rstd = rsqrtf(var + 1e-5f);

    float4 g = reinterpret_cast<const float4*>(gamma)[lane];
    float4 bb = reinterpret_cast<const float4*>(beta)[lane];
    float4 y = make_float4((v.x - mean) * rstd * g.x + bb.x,
                           (v.y - mean) * rstd * g.y + bb.y,
                           (v.z - mean) * rstd * g.z + bb.z,
                           (v.w - mean) * rstd * g.w + bb.w);

    float ss = y.x * y.x + y.y * y.y + y.z * y.z + y.w * y.w;
    ss = warp_sum(ss);
    float vnorm = sqrtf(ss);
    float sc = sqrtK * sinhf(vnorm / sqrtK) / fmaxf(vnorm, 1e-7f);

    float4 o = make_float4(y.x * sc, y.y * sc, y.z * sc, y.w * sc);
    reinterpret_cast<float4*>(out + (size_t)w * D)[lane] = o;
}

// ---------------------------------------------------------------------------
extern "C" void kernel_launch(void* const* d_in, const int* in_sizes, int n_in,
                              void* d_out, int out_size) {
    const float* x_hyp      = (const float*)d_in[0];
    const void*  ei         = d_in[1];
    const float* W          = (const float*)d_in[2];
    const float* b          = (const float*)d_in[3];
    const float* gamma      = (const float*)d_in[4];
    const float* beta       = (const float*)d_in[5];
    const float* curv       = (const float*)d_in[6];

    int N = in_sizes[0] / D;
    int E = in_sizes[1] / 2;
    int L = in_sizes[6];

    float *xtan, *xbuf;
    __half2* xl16;
    int *deg, *rowstart, *cursor, *incl, *bsum, *csr;
    cudaGetSymbolAddress((void**)&xtan, g_xtan);
    cudaGetSymbolAddress((void**)&xbuf, g_x);
    cudaGetSymbolAddress((void**)&xl16, g_xl16);
    cudaGetSymbolAddress((void**)&deg,  g_deg);
    cudaGetSymbolAddress((void**)&rowstart, g_rowstart);
    cudaGetSymbolAddress((void**)&cursor, g_cursor);
    cudaGetSymbolAddress((void**)&incl, g_incl);
    cudaGetSymbolAddress((void**)&bsum, g_bsum);
    cudaGetSymbolAddress((void**)&csr,  g_csr);

    int nb = (N + 255) / 256;

    // One-time per call: dtype detect, degree, scan, CSR fill.
    cudaMemsetAsync(deg, 0, (size_t)N * sizeof(int));
    cudaMemsetAsync(cursor, 0, (size_t)N * sizeof(int));
    k_detect<<<1, 256>>>((const long long*)ei, E, (long long)N);
    k_hist<<<(E + 255) / 256, 256>>>(ei, deg, E, N);
    k_scanA<<<nb, 256>>>(deg, incl, bsum, N);
    k_scanB<<<1, 256>>>(bsum, nb);
    k_scanC<<<nb, 256>>>(incl, bsum, rowstart, N);
    k_fill<<<(E + 255) / 256, 256>>>(ei, rowstart, cursor, csr, E, N);

    int rowBlocks = (N * 32 + 255) / 256;        // warp-per-row kernels

    const float* xin = x_hyp;
    for (int l = 0; l < L; l++) {
        k_gemm_fused<<<(N + 127) / 128, 256>>>(xin, W + (size_t)l * D * D,
                                               b + (size_t)l * D, xtan, xl16,
                                               curv, l, N);
        float* out = (l == L - 1) ? (float*)d_out : xbuf;
        k_aggfinal<<<rowBlocks, 256>>>(rowstart, csr, xl16, xtan, deg,
                                       gamma + (size_t)l * D, beta + (size_t)l * D,
                                       curv, l, out, N);
        xin = xbuf;
    }
}

// round 9
// speedup vs baseline: 2.2359x; 1.0403x over previous
#include <cuda_runtime.h>
#include <cuda_fp16.h>
#include <math.h>

#define D 128
#define MAXN 65536
#define MAXE 1100000

// Scratch (allocation-free rule: __device__ globals)
__device__ __half2 g_xt16[MAXN * (D / 2)];
__device__ float   g_x[MAXN * D];
__device__ __half2 g_xl16[MAXN * (D / 2)];
__device__ int     g_deg[MAXN];
__device__ int     g_cursor[MAXN];
__device__ int     g_incl[MAXN];
__device__ int     g_bsum[512];
__device__ int     g_csr[MAXE];
__device__ int     g_is64;

__device__ __forceinline__ float warp_sum(float v) {
#pragma unroll
    for (int o = 16; o; o >>= 1) v += __shfl_xor_sync(0xFFFFFFFFu, v, o);
    return v;
}

__device__ __forceinline__ float clip_c(float c) {
    return fminf(fmaxf(c, 0.1f), 10.0f);
}

__device__ __forceinline__ unsigned smem_u32(const void* p) {
    return (unsigned)__cvta_generic_to_shared(p);
}

// ---------------------------------------------------------------------------
// Fused: zero deg+cursor (all blocks) + dtype detect (block 0).
// ---------------------------------------------------------------------------
__global__ void k_detect_zero(const long long* __restrict__ ei, int E, long long N,
                              int* __restrict__ deg, int* __restrict__ cursor,
                              int Ni) {
    int gid = blockIdx.x * 256 + threadIdx.x;
    if (gid < Ni) { deg[gid] = 0; cursor[gid] = 0; }
    if (blockIdx.x == 0) {
        int tid = threadIdx.x;
        int n = E < 1024 ? E : 1024;
        int bad = 0;
        for (int i = tid; i < n; i += 256) {
            long long v = ei[i];
            if (v < 0 || v >= N) bad = 1;
        }
        int any = __syncthreads_or(bad);
        if (tid == 0) g_is64 = !any;
    }
}

// ---------------------------------------------------------------------------
// In-degree histogram straight from ei (dtype-branched).
// ---------------------------------------------------------------------------
__global__ void k_hist(const void* __restrict__ ei, int* __restrict__ deg,
                       int E, int N) {
    int e = blockIdx.x * blockDim.x + threadIdx.x;
    if (e >= E) return;
    long long d;
    if (g_is64) d = ((const long long*)ei)[(size_t)E + e];
    else        d = ((const int*)ei)[(size_t)E + e];
    int di = (int)min(max(d, 0LL), (long long)(N - 1));
    atomicAdd(&deg[di], 1);
}

// ---------------------------------------------------------------------------
// 2-phase prefix scan: scanA -> per-block inclusive + block sums,
// scanB -> exclusive block offsets. rowstart reconstructed inline by readers:
//   rowstart[g+1] = incl[g] + bsum[g>>8]
// ---------------------------------------------------------------------------
__global__ void k_scanA(const int* __restrict__ deg, int* __restrict__ incl,
                        int* __restrict__ bsum, int N) {
    __shared__ int wsum[8];
    int tid = threadIdx.x, lane = tid & 31, warp = tid >> 5;
    int gid = blockIdx.x * 256 + tid;
    int v = (gid < N) ? deg[gid] : 0;
    int x = v;
#pragma unroll
    for (int o = 1; o < 32; o <<= 1) {
        int y = __shfl_up_sync(0xFFFFFFFFu, x, o);
        if (lane >= o) x += y;
    }
    if (lane == 31) wsum[warp] = x;
    __syncthreads();
    if (warp == 0) {
        int s = (lane < 8) ? wsum[lane] : 0;
        int y = s;
#pragma unroll
        for (int o = 1; o < 8; o <<= 1) {
            int z = __shfl_up_sync(0xFFFFFFFFu, y, o);
            if (lane >= o) y += z;
        }
        if (lane < 8) wsum[lane] = y - s;   // exclusive warp offset
    }
    __syncthreads();
    int inclv = x + wsum[warp];
    if (gid < N) incl[gid] = inclv;
    if (tid == 255) bsum[blockIdx.x] = inclv;
}

__global__ void k_scanB(int* __restrict__ bsum, int nb) {
    __shared__ int wsum[8];
    int tid = threadIdx.x, lane = tid & 31, warp = tid >> 5;
    int v = (tid < nb) ? bsum[tid] : 0;
    int x = v;
#pragma unroll
    for (int o = 1; o < 32; o <<= 1) {
        int y = __shfl_up_sync(0xFFFFFFFFu, x, o);
        if (lane >= o) x += y;
    }
    if (lane == 31) wsum[warp] = x;
    __syncthreads();
    if (warp == 0) {
        int s = (lane < 8) ? wsum[lane] : 0;
        int y = s;
#pragma unroll
        for (int o = 1; o < 8; o <<= 1) {
            int z = __shfl_up_sync(0xFFFFFFFFu, y, o);
            if (lane >= o) y += z;
        }
        if (lane < 8) wsum[lane] = y - s;
    }
    __syncthreads();
    if (tid < nb) bsum[tid] = x + wsum[warp] - v;   // exclusive block offset
}

// ---------------------------------------------------------------------------
// CSR fill straight from ei (dtype-branched, clamped), rowstart inline.
// ---------------------------------------------------------------------------
__global__ void k_fill(const void* __restrict__ ei,
                       const int* __restrict__ incl, const int* __restrict__ bsum,
                       int* __restrict__ cursor, int* __restrict__ csr,
                       int E, int N) {
    int e = blockIdx.x * blockDim.x + threadIdx.x;
    if (e >= E) return;
    long long s, d;
    if (g_is64) {
        const long long* p = (const long long*)ei;
        s = p[e];
        d = p[(size_t)E + e];
    } else {
        const int* p = (const int*)ei;
        s = p[e];
        d = p[(size_t)E + e];
    }
    int si = (int)min(max(s, 0LL), (long long)(N - 1));
    int di = (int)min(max(d, 0LL), (long long)(N - 1));
    int rs = (di > 0) ? (incl[di - 1] + bsum[(di - 1) >> 8]) : 0;
    int pos = rs + atomicAdd(&cursor[di], 1);
    csr[pos] = si;
}

// ---------------------------------------------------------------------------
// Fused logmap + HMMA GEMM: xt16 = logmap(x) (fp16); x_lin = xtan@W^T+b (fp16).
// Block: 128 rows x 128 cols, 8 warps; warp w owns rows w*16..w*16+15.
// mma.sync.m16n8k16 f16*f16+f32; 16 n-tiles x 4 f32 accumulators per thread.
// ---------------------------------------------------------------------------
__global__ void __launch_bounds__(256) k_gemm_fused(
        const float* __restrict__ xin, const float* __restrict__ W,
        const float* __restrict__ b, __half2* __restrict__ xt16,
        __half2* __restrict__ xl16, const float* __restrict__ curv,
        int l, int N) {
    __shared__ __half As[128][136];   // 34816 B
    __shared__ __half Bs[128][48];    // 12288 B  (total 46 KB)
    int tid = threadIdx.x;
    int lane = tid & 31;
    int wid = tid >> 5;
    int row0 = blockIdx.x * 128;
    int m0 = wid * 16;

    float c = clip_c(curv[l]);
    float K = 1.0f / c;
    float sqrtK = sqrtf(K);

    // Stage 1: load x rows, logmap, write xt16 (fp16) + As (fp16).
#pragma unroll
    for (int i = 0; i < 16; i++) {
        int row = m0 + i;
        int grow = row0 + row;
        float4 v = make_float4(0.f, 0.f, 0.f, 0.f);
        if (grow < N)
            v = __ldg(reinterpret_cast<const float4*>(xin + (size_t)grow * D) + lane);
        float ss = v.x * v.x + v.y * v.y + v.z * v.z + v.w * v.w;
        ss = warp_sum(ss);
        float xnorm = sqrtf(ss);
        float t = sqrtf(K + ss);
        float theta = acoshf(fmaxf(t / sqrtK, 1.0f + 1e-7f));
        float s = sqrtK * theta / fmaxf(xnorm, 1e-7f);
        v.x *= s; v.y *= s; v.z *= s; v.w *= s;
        __half2 h0 = __float22half2_rn(make_float2(v.x, v.y));
        __half2 h1 = __float22half2_rn(make_float2(v.z, v.w));
        uint2 u;
        u.x = *reinterpret_cast<unsigned*>(&h0);
        u.y = *reinterpret_cast<unsigned*>(&h1);
        if (grow < N)
            *reinterpret_cast<uint2*>(xt16 + (size_t)grow * (D / 2) + lane * 2) = u;
        *reinterpret_cast<uint2*>(&As[row][lane * 4]) = u;
    }

    float acc[16][4];
#pragma unroll
    for (int nt = 0; nt < 16; nt++)
#pragma unroll
        for (int q = 0; q < 4; q++) acc[nt][q] = 0.0f;

    // ldmatrix lane address components
    int a_rr = lane & 7;
    int a_sel = lane >> 3;                  // 0..3
    int a_row = m0 + a_rr + ((a_sel & 1) ? 8 : 0);
    int a_koff = (a_sel >> 1) ? 8 : 0;
    int b_rr = lane & 7;
    int b_koff = ((lane >> 3) & 1) ? 8 : 0;

    // W staging assignment: thread -> row j, k-half
    int wj = tid >> 1;
    int wkh = (tid & 1) * 16;

    for (int kc = 0; kc < 4; kc++) {
        __syncthreads();   // Bs reuse barrier (also covers As visibility, iter 0)
        // stage W chunk: Bs[j][kk] = (half)W[j][kc*32+kk]
        {
            const float4* wp = reinterpret_cast<const float4*>(
                &W[(size_t)wj * D + kc * 32 + wkh]);
            float4 w0 = __ldg(wp + 0);
            float4 w1 = __ldg(wp + 1);
            float4 w2 = __ldg(wp + 2);
            float4 w3 = __ldg(wp + 3);
            __half2 h0 = __float22half2_rn(make_float2(w0.x, w0.y));
            __half2 h1 = __float22half2_rn(make_float2(w0.z, w0.w));
            __half2 h2 = __float22half2_rn(make_float2(w1.x, w1.y));
            __half2 h3 = __float22half2_rn(make_float2(w1.z, w1.w));
            __half2 h4 = __float22half2_rn(make_float2(w2.x, w2.y));
            __half2 h5 = __float22half2_rn(make_float2(w2.z, w2.w));
            __half2 h6 = __float22half2_rn(make_float2(w3.x, w3.y));
            __half2 h7 = __float22half2_rn(make_float2(w3.z, w3.w));
            uint4 u0, u1;
            u0.x = *reinterpret_cast<unsigned*>(&h0);
            u0.y = *reinterpret_cast<unsigned*>(&h1);
            u0.z = *reinterpret_cast<unsigned*>(&h2);
            u0.w = *reinterpret_cast<unsigned*>(&h3);
            u1.x = *reinterpret_cast<unsigned*>(&h4);
            u1.y = *reinterpret_cast<unsigned*>(&h5);
            u1.z = *reinterpret_cast<unsigned*>(&h6);
            u1.w = *reinterpret_cast<unsigned*>(&h7);
            *reinterpret_cast<uint4*>(&Bs[wj][wkh + 0]) = u0;
            *reinterpret_cast<uint4*>(&Bs[wj][wkh + 8]) = u1;
        }
        __syncthreads();

#pragma unroll
        for (int s = 0; s < 2; s++) {
            int kg = kc * 32 + s * 16;      // global k for A
            int ks = s * 16;                // chunk-local k for B
            unsigned a0, a1, a2, a3;
            unsigned aaddr = smem_u32(&As[a_row][kg + a_koff]);
            asm volatile(
                "ldmatrix.sync.aligned.m8n8.x4.shared.b16 {%0,%1,%2,%3}, [%4];"
                : "=r"(a0), "=r"(a1), "=r"(a2), "=r"(a3) : "r"(aaddr));
#pragma unroll
            for (int nt = 0; nt < 16; nt++) {
                unsigned b0, b1;
                unsigned baddr = smem_u32(&Bs[nt * 8 + b_rr][ks + b_koff]);
                asm volatile(
                    "ldmatrix.sync.aligned.m8n8.x2.shared.b16 {%0,%1}, [%2];"
                    : "=r"(b0), "=r"(b1) : "r"(baddr));
                asm volatile(
                    "mma.sync.aligned.m16n8k16.row.col.f32.f16.f16.f32 "
                    "{%0,%1,%2,%3}, {%4,%5,%6,%7}, {%8,%9}, {%0,%1,%2,%3};"
                    : "+f"(acc[nt][0]), "+f"(acc[nt][1]),
                      "+f"(acc[nt][2]), "+f"(acc[nt][3])
                    : "r"(a0), "r"(a1), "r"(a2), "r"(a3), "r"(b0), "r"(b1));
            }
        }
    }

    // Epilogue: add bias, convert to fp16, store xl16.
    int gid = lane >> 2;     // C-fragment row group
    int tig = lane & 3;      // C-fragment col pair
    int row1 = row0 + m0 + gid;
    int row2 = row1 + 8;
#pragma unroll
    for (int nt = 0; nt < 16; nt++) {
        int col = nt * 8 + 2 * tig;
        float2 bv = *reinterpret_cast<const float2*>(&b[col]);
        if (row1 < N) {
            __half2 h = __float22half2_rn(
                make_float2(acc[nt][0] + bv.x, acc[nt][1] + bv.y));
            xl16[(size_t)row1 * (D / 2) + (col >> 1)] = h;
        }
        if (row2 < N) {
            __half2 h = __float22half2_rn(
                make_float2(acc[nt][2] + bv.x, acc[nt][3] + bv.y));
            xl16[(size_t)row2 * (D / 2) + (col >> 1)] = h;
        }
    }
}

// ---------------------------------------------------------------------------
// Fused CSR aggregation (fp16 gather, fp32 accumulate) + mean + residual +
// LN + expmap. One warp per destination row; rowstart inline from incl/bsum;
// deg = end - beg (no separate deg read).
// ---------------------------------------------------------------------------
__global__ void k_aggfinal(const int* __restrict__ incl, const int* __restrict__ bsum,
                           const int* __restrict__ csr,
                           const __half2* __restrict__ xl16,
                           const __half2* __restrict__ xt16,
                           const float* __restrict__ gamma, const float* __restrict__ beta,
                           const float* __restrict__ curv, int l,
                           float* __restrict__ out, int N) {
    int w = (blockIdx.x * blockDim.x + threadIdx.x) >> 5;
    int lane = threadIdx.x & 31;
    if (w >= N) return;

    int beg = (w > 0) ? (incl[w - 1] + bsum[(w - 1) >> 8]) : 0;
    int end = incl[w] + bsum[w >> 8];
    float4 acc = make_float4(0.f, 0.f, 0.f, 0.f);
    const uint2* xlu = reinterpret_cast<const uint2*>(xl16);   // 1 uint2 = 4 halves

    int e = beg;
    for (; e + 8 <= end; e += 8) {
        int sidx[8];
#pragma unroll
        for (int t = 0; t < 8; t++) sidx[t] = __ldg(&csr[e + t]);
        uint2 q[8];
#pragma unroll
        for (int t = 0; t < 8; t++)
            q[t] = __ldg(&xlu[(size_t)sidx[t] * 32 + lane]);
#pragma unroll
        for (int t = 0; t < 8; t++) {
            float2 f0 = __half22float2(*reinterpret_cast<__half2*>(&q[t].x));
            float2 f1 = __half22float2(*reinterpret_cast<__half2*>(&q[t].y));
            acc.x += f0.x; acc.y += f0.y; acc.z += f1.x; acc.w += f1.y;
        }
    }
    if (e + 4 <= end) {
        int sidx[4];
#pragma unroll
        for (int t = 0; t < 4; t++) sidx[t] = __ldg(&csr[e + t]);
        uint2 q[4];
#pragma unroll
        for (int t = 0; t < 4; t++)
            q[t] = __ldg(&xlu[(size_t)sidx[t] * 32 + lane]);
#pragma unroll
        for (int t = 0; t < 4; t++) {
            float2 f0 = __half22float2(*reinterpret_cast<__half2*>(&q[t].x));
            float2 f1 = __half22float2(*reinterpret_cast<__half2*>(&q[t].y));
            acc.x += f0.x; acc.y += f0.y; acc.z += f1.x; acc.w += f1.y;
        }
        e += 4;
    }
    for (; e < end; e++) {
        int s = __ldg(&csr[e]);
        uint2 q = __ldg(&xlu[(size_t)s * 32 + lane]);
        float2 f0 = __half22float2(*reinterpret_cast<__half2*>(&q.x));
        float2 f1 = __half22float2(*reinterpret_cast<__half2*>(&q.y));
        acc.x += f0.x; acc.y += f0.y; acc.z += f1.x; acc.w += f1.y;
    }

    float c = clip_c(curv[l]);
    float K = 1.0f / c;
    float sqrtK = sqrtf(K);
    int dg = end - beg;
    float rcn = 1.0f / (float)(dg > 1 ? dg : 1);

    uint2 tu = __ldg(reinterpret_cast<const uint2*>(xt16 + (size_t)w * (D / 2)) + lane);
    float2 t0 = __half22float2(*reinterpret_cast<__half2*>(&tu.x));
    float2 t1 = __half22float2(*reinterpret_cast<__half2*>(&tu.y));
    float4 v = make_float4(t0.x + acc.x * rcn, t0.y + acc.y * rcn,
                           t1.x + acc.z * rcn, t1.y + acc.w * rcn);

    float s1 = v.x + v.y + v.z + v.w;
    float s2 = v.x * v.x + v.y * v.y + v.z * v.z + v.w * v.w;
    s1 = warp_sum(s1);
    s2 = warp_sum(s2);
    float mean = s1 * (1.0f / D);
    float var = s2 * (1.0f / D) - mean * mean;
    float rstd = rsqrtf(var + 1e-5f);

    float4 g = reinterpret_cast<const float4*>(gamma)[lane];
    float4 bb = reinterpret_cast<const float4*>(beta)[lane];
    float4 y = make_float4((v.x - mean) * rstd * g.x + bb.x,
                           (v.y - mean) * rstd * g.y + bb.y,
                           (v.z - mean) * rstd * g.z + bb.z,
                           (v.w - mean) * rstd * g.w + bb.w);

    float ss = y.x * y.x + y.y * y.y + y.z * y.z + y.w * y.w;
    ss = warp_sum(ss);
    float vnorm = sqrtf(ss);
    float sc = sqrtK * sinhf(vnorm / sqrtK) / fmaxf(vnorm, 1e-7f);

    float4 o = make_float4(y.x * sc, y.y * sc, y.z * sc, y.w * sc);
    reinterpret_cast<float4*>(out + (size_t)w * D)[lane] = o;
}

// ---------------------------------------------------------------------------
extern "C" void kernel_launch(void* const* d_in, const int* in_sizes, int n_in,
                              void* d_out, int out_size) {
    const float* x_hyp      = (const float*)d_in[0];
    const void*  ei         = d_in[1];
    const float* W          = (const float*)d_in[2];
    const float* b          = (const float*)d_in[3];
    const float* gamma      = (const float*)d_in[4];
    const float* beta       = (const float*)d_in[5];
    const float* curv       = (const float*)d_in[6];

    int N = in_sizes[0] / D;
    int E = in_sizes[1] / 2;
    int L = in_sizes[6];

    float* xbuf;
    __half2 *xl16, *xt16;
    int *deg, *cursor, *incl, *bsum, *csr;
    cudaGetSymbolAddress((void**)&xt16, g_xt16);
    cudaGetSymbolAddress((void**)&xbuf, g_x);
    cudaGetSymbolAddress((void**)&xl16, g_xl16);
    cudaGetSymbolAddress((void**)&deg,  g_deg);
    cudaGetSymbolAddress((void**)&cursor, g_cursor);
    cudaGetSymbolAddress((void**)&incl, g_incl);
    cudaGetSymbolAddress((void**)&bsum, g_bsum);
    cudaGetSymbolAddress((void**)&csr,  g_csr);

    int nb = (N + 255) / 256;

    // One-time CSR build: 5 launches (so launch #6 = gemm layer 0 for ncu).
    k_detect_zero<<<nb, 256>>>((const long long*)ei, E, (long long)N, deg, cursor, N);
    k_hist<<<(E + 255) / 256, 256>>>(ei, deg, E, N);
    k_scanA<<<nb, 256>>>(deg, incl, bsum, N);
    k_scanB<<<1, 256>>>(bsum, nb);
    k_fill<<<(E + 255) / 256, 256>>>(ei, incl, bsum, cursor, csr, E, N);

    int rowBlocks = (N * 32 + 255) / 256;        // warp-per-row kernels

    const float* xin = x_hyp;
    for (int l = 0; l < L; l++) {
        k_gemm_fused<<<(N + 127) / 128, 256>>>(xin, W + (size_t)l * D * D,
                                               b + (size_t)l * D, xt16, xl16,
                                               curv, l, N);
        float* out = (l == L - 1) ? (float*)d_out : xbuf;
        k_aggfinal<<<rowBlocks, 256>>>(incl, bsum, csr, xl16, xt16,
                                       gamma + (size_t)l * D, beta + (size_t)l * D,
                                       curv, l, out, N);
        xin = xbuf;
    }
}

// round 10
// speedup vs baseline: 2.4014x; 1.0740x over previous
#include <cuda_runtime.h>
#include <cuda_fp16.h>
#include <math.h>

#define D 128
#define MAXN 65536
#define MAXE 1100000

// Scratch (allocation-free rule: __device__ globals)
__device__ __half2  g_xt16[MAXN * (D / 2)];
__device__ float    g_x[MAXN * D];
__device__ __half2  g_xl16[MAXN * (D / 2)];
__device__ int      g_deg[MAXN];
__device__ int      g_cursor[MAXN];
__device__ int      g_incl[MAXN];
__device__ int      g_bsum[512];
__device__ int      g_csr[MAXE];
__device__ int      g_is64;
__device__ unsigned g_rowcur;

__device__ __forceinline__ float warp_sum(float v) {
#pragma unroll
    for (int o = 16; o; o >>= 1) v += __shfl_xor_sync(0xFFFFFFFFu, v, o);
    return v;
}

__device__ __forceinline__ float clip_c(float c) {
    return fminf(fmaxf(c, 0.1f), 10.0f);
}

__device__ __forceinline__ unsigned smem_u32(const void* p) {
    return (unsigned)__cvta_generic_to_shared(p);
}

// ---------------------------------------------------------------------------
// Fused: zero deg+cursor (all blocks) + dtype detect (block 0).
// ---------------------------------------------------------------------------
__global__ void k_detect_zero(const long long* __restrict__ ei, int E, long long N,
                              int* __restrict__ deg, int* __restrict__ cursor,
                              int Ni) {
    int gid = blockIdx.x * 256 + threadIdx.x;
    if (gid < Ni) { deg[gid] = 0; cursor[gid] = 0; }
    if (blockIdx.x == 0) {
        int tid = threadIdx.x;
        int n = E < 1024 ? E : 1024;
        int bad = 0;
        for (int i = tid; i < n; i += 256) {
            long long v = ei[i];
            if (v < 0 || v >= N) bad = 1;
        }
        int any = __syncthreads_or(bad);
        if (tid == 0) g_is64 = !any;
    }
}

// ---------------------------------------------------------------------------
// In-degree histogram straight from ei (dtype-branched).
// ---------------------------------------------------------------------------
__global__ void k_hist(const void* __restrict__ ei, int* __restrict__ deg,
                       int E, int N) {
    int e = blockIdx.x * blockDim.x + threadIdx.x;
    if (e >= E) return;
    long long d;
    if (g_is64) d = ((const long long*)ei)[(size_t)E + e];
    else        d = ((const int*)ei)[(size_t)E + e];
    int di = (int)min(max(d, 0LL), (long long)(N - 1));
    atomicAdd(&deg[di], 1);
}

// ---------------------------------------------------------------------------
// 2-phase prefix scan: scanA -> per-block inclusive + block sums,
// scanB -> exclusive block offsets. rowstart reconstructed inline by readers:
//   rowstart[g+1] = incl[g] + bsum[g>>8]
// ---------------------------------------------------------------------------
__global__ void k_scanA(const int* __restrict__ deg, int* __restrict__ incl,
                        int* __restrict__ bsum, int N) {
    __shared__ int wsum[8];
    int tid = threadIdx.x, lane = tid & 31, warp = tid >> 5;
    int gid = blockIdx.x * 256 + tid;
    int v = (gid < N) ? deg[gid] : 0;
    int x = v;
#pragma unroll
    for (int o = 1; o < 32; o <<= 1) {
        int y = __shfl_up_sync(0xFFFFFFFFu, x, o);
        if (lane >= o) x += y;
    }
    if (lane == 31) wsum[warp] = x;
    __syncthreads();
    if (warp == 0) {
        int s = (lane < 8) ? wsum[lane] : 0;
        int y = s;
#pragma unroll
        for (int o = 1; o < 8; o <<= 1) {
            int z = __shfl_up_sync(0xFFFFFFFFu, y, o);
            if (lane >= o) y += z;
        }
        if (lane < 8) wsum[lane] = y - s;   // exclusive warp offset
    }
    __syncthreads();
    int inclv = x + wsum[warp];
    if (gid < N) incl[gid] = inclv;
    if (tid == 255) bsum[blockIdx.x] = inclv;
}

__global__ void k_scanB(int* __restrict__ bsum, int nb) {
    __shared__ int wsum[8];
    int tid = threadIdx.x, lane = tid & 31, warp = tid >> 5;
    int v = (tid < nb) ? bsum[tid] : 0;
    int x = v;
#pragma unroll
    for (int o = 1; o < 32; o <<= 1) {
        int y = __shfl_up_sync(0xFFFFFFFFu, x, o);
        if (lane >= o) x += y;
    }
    if (lane == 31) wsum[warp] = x;
    __syncthreads();
    if (warp == 0) {
        int s = (lane < 8) ? wsum[lane] : 0;
        int y = s;
#pragma unroll
        for (int o = 1; o < 8; o <<= 1) {
            int z = __shfl_up_sync(0xFFFFFFFFu, y, o);
            if (lane >= o) y += z;
        }
        if (lane < 8) wsum[lane] = y - s;
    }
    __syncthreads();
    if (tid < nb) bsum[tid] = x + wsum[warp] - v;   // exclusive block offset
}

// ---------------------------------------------------------------------------
// CSR fill straight from ei (dtype-branched, clamped), rowstart inline.
// ---------------------------------------------------------------------------
__global__ void k_fill(const void* __restrict__ ei,
                       const int* __restrict__ incl, const int* __restrict__ bsum,
                       int* __restrict__ cursor, int* __restrict__ csr,
                       int E, int N) {
    int e = blockIdx.x * blockDim.x + threadIdx.x;
    if (e >= E) return;
    long long s, d;
    if (g_is64) {
        const long long* p = (const long long*)ei;
        s = p[e];
        d = p[(size_t)E + e];
    } else {
        const int* p = (const int*)ei;
        s = p[e];
        d = p[(size_t)E + e];
    }
    int si = (int)min(max(s, 0LL), (long long)(N - 1));
    int di = (int)min(max(d, 0LL), (long long)(N - 1));
    int rs = (di > 0) ? (incl[di - 1] + bsum[(di - 1) >> 8]) : 0;
    int pos = rs + atomicAdd(&cursor[di], 1);
    csr[pos] = si;
}

// ---------------------------------------------------------------------------
// Fused logmap + HMMA GEMM: xt16 = logmap(x) (fp16); x_lin = xtan@W^T+b (fp16).
// Block: 128 rows x 128 cols, 8 warps; warp w owns rows w*16..w*16+15.
// Bs pitch 40 halves (80B = 5x16B -> conflict-free LDSM); W register-prefetch;
// B fragments via ldmatrix.x4 (2 n-tiles per instruction).
// Block 0 thread 0 also resets the agg row cursor (ordered by kernel boundary).
// ---------------------------------------------------------------------------
__global__ void __launch_bounds__(256) k_gemm_fused(
        const float* __restrict__ xin, const float* __restrict__ W,
        const float* __restrict__ b, __half2* __restrict__ xt16,
        __half2* __restrict__ xl16, const float* __restrict__ curv,
        int l, int N) {
    __shared__ __half As[128][136];   // 34816 B
    __shared__ __half Bs[128][40];    // 10240 B  (total 44 KB)
    int tid = threadIdx.x;
    int lane = tid & 31;
    int wid = tid >> 5;
    int row0 = blockIdx.x * 128;
    int m0 = wid * 16;

    if (blockIdx.x == 0 && tid == 0) g_rowcur = 0u;   // reset agg cursor

    float c = clip_c(curv[l]);
    float K = 1.0f / c;
    float sqrtK = sqrtf(K);

    // Stage 1: load x rows, logmap, write xt16 (fp16) + As (fp16).
#pragma unroll
    for (int i = 0; i < 16; i++) {
        int row = m0 + i;
        int grow = row0 + row;
        float4 v = make_float4(0.f, 0.f, 0.f, 0.f);
        if (grow < N)
            v = __ldg(reinterpret_cast<const float4*>(xin + (size_t)grow * D) + lane);
        float ss = v.x * v.x + v.y * v.y + v.z * v.z + v.w * v.w;
        ss = warp_sum(ss);
        float xnorm = sqrtf(ss);
        float t = sqrtf(K + ss);
        float theta = acoshf(fmaxf(t / sqrtK, 1.0f + 1e-7f));
        float s = sqrtK * theta / fmaxf(xnorm, 1e-7f);
        v.x *= s; v.y *= s; v.z *= s; v.w *= s;
        __half2 h0 = __float22half2_rn(make_float2(v.x, v.y));
        __half2 h1 = __float22half2_rn(make_float2(v.z, v.w));
        uint2 u;
        u.x = *reinterpret_cast<unsigned*>(&h0);
        u.y = *reinterpret_cast<unsigned*>(&h1);
        if (grow < N)
            *reinterpret_cast<uint2*>(xt16 + (size_t)grow * (D / 2) + lane * 2) = u;
        *reinterpret_cast<uint2*>(&As[row][lane * 4]) = u;
    }

    float acc[16][4];
#pragma unroll
    for (int nt = 0; nt < 16; nt++)
#pragma unroll
        for (int q = 0; q < 4; q++) acc[nt][q] = 0.0f;

    // ldmatrix lane address components
    int a_rr = lane & 7;
    int a_sel = lane >> 3;                  // 0..3
    int a_row = m0 + a_rr + ((a_sel & 1) ? 8 : 0);
    int a_koff = (a_sel >> 1) ? 8 : 0;
    int b_row2 = (lane & 7) + ((lane & 16) ? 8 : 0);
    int b_col2 = (lane & 8) ? 8 : 0;

    // W staging assignment: thread -> row j, k-half
    int wj = tid >> 1;
    int wkh = (tid & 1) * 16;

    // prefetch W chunk 0 into registers
    float4 wreg[4];
    {
        const float4* wp = reinterpret_cast<const float4*>(&W[(size_t)wj * D + wkh]);
#pragma unroll
        for (int p = 0; p < 4; p++) wreg[p] = __ldg(wp + p);
    }

    for (int kc = 0; kc < 4; kc++) {
        __syncthreads();   // previous Bs consumed; kc=0 also covers As writes
        // store registered W chunk to Bs (fp16)
        {
            __half2 h0 = __float22half2_rn(make_float2(wreg[0].x, wreg[0].y));
            __half2 h1 = __float22half2_rn(make_float2(wreg[0].z, wreg[0].w));
            __half2 h2 = __float22half2_rn(make_float2(wreg[1].x, wreg[1].y));
            __half2 h3 = __float22half2_rn(make_float2(wreg[1].z, wreg[1].w));
            __half2 h4 = __float22half2_rn(make_float2(wreg[2].x, wreg[2].y));
            __half2 h5 = __float22half2_rn(make_float2(wreg[2].z, wreg[2].w));
            __half2 h6 = __float22half2_rn(make_float2(wreg[3].x, wreg[3].y));
            __half2 h7 = __float22half2_rn(make_float2(wreg[3].z, wreg[3].w));
            uint4 u0, u1;
            u0.x = *reinterpret_cast<unsigned*>(&h0);
            u0.y = *reinterpret_cast<unsigned*>(&h1);
            u0.z = *reinterpret_cast<unsigned*>(&h2);
            u0.w = *reinterpret_cast<unsigned*>(&h3);
            u1.x = *reinterpret_cast<unsigned*>(&h4);
            u1.y = *reinterpret_cast<unsigned*>(&h5);
            u1.z = *reinterpret_cast<unsigned*>(&h6);
            u1.w = *reinterpret_cast<unsigned*>(&h7);
            *reinterpret_cast<uint4*>(&Bs[wj][wkh + 0]) = u0;
            *reinterpret_cast<uint4*>(&Bs[wj][wkh + 8]) = u1;
        }
        // prefetch next W chunk (latency overlaps sync + MMA below)
        if (kc < 3) {
            const float4* wp = reinterpret_cast<const float4*>(
                &W[(size_t)wj * D + (kc + 1) * 32 + wkh]);
#pragma unroll
            for (int p = 0; p < 4; p++) wreg[p] = __ldg(wp + p);
        }
        __syncthreads();

#pragma unroll
        for (int s = 0; s < 2; s++) {
            int kg = kc * 32 + s * 16;      // global k for A
            int ks = s * 16;                // chunk-local k for B
            unsigned a0, a1, a2, a3;
            unsigned aaddr = smem_u32(&As[a_row][kg + a_koff]);
            asm volatile(
                "ldmatrix.sync.aligned.m8n8.x4.shared.b16 {%0,%1,%2,%3}, [%4];"
                : "=r"(a0), "=r"(a1), "=r"(a2), "=r"(a3) : "r"(aaddr));
#pragma unroll
            for (int p = 0; p < 8; p++) {
                unsigned b0, b1, b2, b3;
                unsigned baddr = smem_u32(&Bs[p * 16 + b_row2][ks + b_col2]);
                asm volatile(
                    "ldmatrix.sync.aligned.m8n8.x4.shared.b16 {%0,%1,%2,%3}, [%4];"
                    : "=r"(b0), "=r"(b1), "=r"(b2), "=r"(b3) : "r"(baddr));
                asm volatile(
                    "mma.sync.aligned.m16n8k16.row.col.f32.f16.f16.f32 "
                    "{%0,%1,%2,%3}, {%4,%5,%6,%7}, {%8,%9}, {%0,%1,%2,%3};"
                    : "+f"(acc[2 * p][0]), "+f"(acc[2 * p][1]),
                      "+f"(acc[2 * p][2]), "+f"(acc[2 * p][3])
                    : "r"(a0), "r"(a1), "r"(a2), "r"(a3), "r"(b0), "r"(b1));
                asm volatile(
                    "mma.sync.aligned.m16n8k16.row.col.f32.f16.f16.f32 "
                    "{%0,%1,%2,%3}, {%4,%5,%6,%7}, {%8,%9}, {%0,%1,%2,%3};"
                    : "+f"(acc[2 * p + 1][0]), "+f"(acc[2 * p + 1][1]),
                      "+f"(acc[2 * p + 1][2]), "+f"(acc[2 * p + 1][3])
                    : "r"(a0), "r"(a1), "r"(a2), "r"(a3), "r"(b2), "r"(b3));
            }
        }
    }

    // Epilogue: add bias, convert to fp16, store xl16.
    int gid = lane >> 2;     // C-fragment row group
    int tig = lane & 3;      // C-fragment col pair
    int row1 = row0 + m0 + gid;
    int row2 = row1 + 8;
#pragma unroll
    for (int nt = 0; nt < 16; nt++) {
        int col = nt * 8 + 2 * tig;
        float2 bv = *reinterpret_cast<const float2*>(&b[col]);
        if (row1 < N) {
            __half2 h = __float22half2_rn(
                make_float2(acc[nt][0] + bv.x, acc[nt][1] + bv.y));
            xl16[(size_t)row1 * (D / 2) + (col >> 1)] = h;
        }
        if (row2 < N) {
            __half2 h = __float22half2_rn(
                make_float2(acc[nt][2] + bv.x, acc[nt][3] + bv.y));
            xl16[(size_t)row2 * (D / 2) + (col >> 1)] = h;
        }
    }
}

// ---------------------------------------------------------------------------
// Fused CSR aggregation (fp16 gather, fp32 accumulate) + mean + residual +
// LN + expmap. Dynamic scheduling: warps grab 4-row chunks from a global
// cursor (reset by the preceding gemm) -> no warp/block load imbalance.
// ---------------------------------------------------------------------------
__global__ void k_aggfinal(const int* __restrict__ incl, const int* __restrict__ bsum,
                           const int* __restrict__ csr,
                           const __half2* __restrict__ xl16,
                           const __half2* __restrict__ xt16,
                           const float* __restrict__ gamma, const float* __restrict__ beta,
                           const float* __restrict__ curv, int l,
                           float* __restrict__ out, int N) {
    int lane = threadIdx.x & 31;
    const uint2* xlu = reinterpret_cast<const uint2*>(xl16);   // 1 uint2 = 4 halves

    float c = clip_c(curv[l]);
    float K = 1.0f / c;
    float sqrtK = sqrtf(K);
    float4 g = reinterpret_cast<const float4*>(gamma)[lane];
    float4 bb = reinterpret_cast<const float4*>(beta)[lane];

    for (;;) {
        int base;
        if (lane == 0) base = (int)atomicAdd(&g_rowcur, 4u);
        base = __shfl_sync(0xFFFFFFFFu, base, 0);
        if (base >= N) return;
        int wend = base + 4 < N ? base + 4 : N;

        for (int w = base; w < wend; w++) {
            int beg = (w > 0) ? (incl[w - 1] + bsum[(w - 1) >> 8]) : 0;
            int end = incl[w] + bsum[w >> 8];
            float4 acc = make_float4(0.f, 0.f, 0.f, 0.f);

            int e = beg;
            for (; e + 8 <= end; e += 8) {
                int sidx[8];
#pragma unroll
                for (int t = 0; t < 8; t++) sidx[t] = __ldg(&csr[e + t]);
                uint2 q[8];
#pragma unroll
                for (int t = 0; t < 8; t++)
                    q[t] = __ldg(&xlu[(size_t)sidx[t] * 32 + lane]);
#pragma unroll
                for (int t = 0; t < 8; t++) {
                    float2 f0 = __half22float2(*reinterpret_cast<__half2*>(&q[t].x));
                    float2 f1 = __half22float2(*reinterpret_cast<__half2*>(&q[t].y));
                    acc.x += f0.x; acc.y += f0.y; acc.z += f1.x; acc.w += f1.y;
                }
            }
            if (e + 4 <= end) {
                int sidx[4];
#pragma unroll
                for (int t = 0; t < 4; t++) sidx[t] = __ldg(&csr[e + t]);
                uint2 q[4];
#pragma unroll
                for (int t = 0; t < 4; t++)
                    q[t] = __ldg(&xlu[(size_t)sidx[t] * 32 + lane]);
#pragma unroll
                for (int t = 0; t < 4; t++) {
                    float2 f0 = __half22float2(*reinterpret_cast<__half2*>(&q[t].x));
                    float2 f1 = __half22float2(*reinterpret_cast<__half2*>(&q[t].y));
                    acc.x += f0.x; acc.y += f0.y; acc.z += f1.x; acc.w += f1.y;
                }
                e += 4;
            }
            for (; e < end; e++) {
                int s = __ldg(&csr[e]);
                uint2 q = __ldg(&xlu[(size_t)s * 32 + lane]);
                float2 f0 = __half22float2(*reinterpret_cast<__half2*>(&q.x));
                float2 f1 = __half22float2(*reinterpret_cast<__half2*>(&q.y));
                acc.x += f0.x; acc.y += f0.y; acc.z += f1.x; acc.w += f1.y;
            }

            int dg = end - beg;
            float rcn = 1.0f / (float)(dg > 1 ? dg : 1);

            uint2 tu = __ldg(reinterpret_cast<const uint2*>(
                xt16 + (size_t)w * (D / 2)) + lane);
            float2 t0 = __half22float2(*reinterpret_cast<__half2*>(&tu.x));
            float2 t1 = __half22float2(*reinterpret_cast<__half2*>(&tu.y));
            float4 v = make_float4(t0.x + acc.x * rcn, t0.y + acc.y * rcn,
                                   t1.x + acc.z * rcn, t1.y + acc.w * rcn);

            float s1 = v.x + v.y + v.z + v.w;
            float s2 = v.x * v.x + v.y * v.y + v.z * v.z + v.w * v.w;
            s1 = warp_sum(s1);
            s2 = warp_sum(s2);
            float mean = s1 * (1.0f / D);
            float var = s2 * (1.0f / D) - mean * mean;
            float rstd = rsqrtf(var + 1e-5f);

            float4 y = make_float4((v.x - mean) * rstd * g.x + bb.x,
                                   (v.y - mean) * rstd * g.y + bb.y,
                                   (v.z - mean) * rstd * g.z + bb.z,
                                   (v.w - mean) * rstd * g.w + bb.w);

            float ss = y.x * y.x + y.y * y.y + y.z * y.z + y.w * y.w;
            ss = warp_sum(ss);
            float vnorm = sqrtf(ss);
            float sc = sqrtK * sinhf(vnorm / sqrtK) / fmaxf(vnorm, 1e-7f);

            float4 o = make_float4(y.x * sc, y.y * sc, y.z * sc, y.w * sc);
            reinterpret_cast<float4*>(out + (size_t)w * D)[lane] = o;
        }
    }
}

// ---------------------------------------------------------------------------
extern "C" void kernel_launch(void* const* d_in, const int* in_sizes, int n_in,
                              void* d_out, int out_size) {
    const float* x_hyp      = (const float*)d_in[0];
    const void*  ei         = d_in[1];
    const float* W          = (const float*)d_in[2];
    const float* b          = (const float*)d_in[3];
    const float* gamma      = (const float*)d_in[4];
    const float* beta       = (const float*)d_in[5];
    const float* curv       = (const float*)d_in[6];

    int N = in_sizes[0] / D;
    int E = in_sizes[1] / 2;
    int L = in_sizes[6];

    float* xbuf;
    __half2 *xl16, *xt16;
    int *deg, *cursor, *incl, *bsum, *csr;
    cudaGetSymbolAddress((void**)&xt16, g_xt16);
    cudaGetSymbolAddress((void**)&xbuf, g_x);
    cudaGetSymbolAddress((void**)&xl16, g_xl16);
    cudaGetSymbolAddress((void**)&deg,  g_deg);
    cudaGetSymbolAddress((void**)&cursor, g_cursor);
    cudaGetSymbolAddress((void**)&incl, g_incl);
    cudaGetSymbolAddress((void**)&bsum, g_bsum);
    cudaGetSymbolAddress((void**)&csr,  g_csr);

    int nb = (N + 255) / 256;

    // One-time CSR build.
    k_detect_zero<<<nb, 256>>>((const long long*)ei, E, (long long)N, deg, cursor, N);
    k_hist<<<(E + 255) / 256, 256>>>(ei, deg, E, N);
    k_scanA<<<nb, 256>>>(deg, incl, bsum, N);
    k_scanB<<<1, 256>>>(bsum, nb);
    k_fill<<<(E + 255) / 256, 256>>>(ei, incl, bsum, cursor, csr, E, N);

    const float* xin = x_hyp;
    for (int l = 0; l < L; l++) {
        k_gemm_fused<<<(N + 127) / 128, 256>>>(xin, W + (size_t)l * D * D,
                                               b + (size_t)l * D, xt16, xl16,
                                               curv, l, N);
        float* out = (l == L - 1) ? (float*)d_out : xbuf;
        k_aggfinal<<<1184, 256>>>(incl, bsum, csr, xl16, xt16,
                                  gamma + (size_t)l * D, beta + (size_t)l * D,
                                  curv, l, out, N);
        xin = xbuf;
    }
}

// round 11
// speedup vs baseline: 2.7549x; 1.1472x over previous
#include <cuda_runtime.h>
#include <cuda_fp16.h>
#include <math.h>

#define D 128
#define MAXN 65536
#define MAXE 1100000

// Scratch (allocation-free rule: __device__ globals)
__device__ __half2  g_xt16[MAXN * (D / 2)];
__device__ __half2  g_xl16[MAXN * (D / 2)];
__device__ int      g_deg[MAXN];
__device__ int      g_cursor[MAXN];
__device__ int      g_incl[MAXN];
__device__ int      g_bsum[512];
__device__ int      g_csr[MAXE];
__device__ int      g_is64;
__device__ unsigned g_rowcur;

__device__ __forceinline__ float warp_sum(float v) {
#pragma unroll
    for (int o = 16; o; o >>= 1) v += __shfl_xor_sync(0xFFFFFFFFu, v, o);
    return v;
}

__device__ __forceinline__ float clip_c(float c) {
    return fminf(fmaxf(c, 0.1f), 10.0f);
}

__device__ __forceinline__ unsigned smem_u32(const void* p) {
    return (unsigned)__cvta_generic_to_shared(p);
}

// ---------------------------------------------------------------------------
// Fused: zero deg+cursor (all blocks) + dtype detect (block 0).
// ---------------------------------------------------------------------------
__global__ void k_detect_zero(const long long* __restrict__ ei, int E, long long N,
                              int* __restrict__ deg, int* __restrict__ cursor,
                              int Ni) {
    int gid = blockIdx.x * 256 + threadIdx.x;
    if (gid < Ni) { deg[gid] = 0; cursor[gid] = 0; }
    if (blockIdx.x == 0) {
        int tid = threadIdx.x;
        int n = E < 1024 ? E : 1024;
        int bad = 0;
        for (int i = tid; i < n; i += 256) {
            long long v = ei[i];
            if (v < 0 || v >= N) bad = 1;
        }
        int any = __syncthreads_or(bad);
        if (tid == 0) g_is64 = !any;
    }
}

// ---------------------------------------------------------------------------
// In-degree histogram straight from ei (dtype-branched).
// ---------------------------------------------------------------------------
__global__ void k_hist(const void* __restrict__ ei, int* __restrict__ deg,
                       int E, int N) {
    int e = blockIdx.x * blockDim.x + threadIdx.x;
    if (e >= E) return;
    long long d;
    if (g_is64) d = ((const long long*)ei)[(size_t)E + e];
    else        d = ((const int*)ei)[(size_t)E + e];
    int di = (int)min(max(d, 0LL), (long long)(N - 1));
    atomicAdd(&deg[di], 1);
}

// ---------------------------------------------------------------------------
// 2-phase prefix scan: scanA -> per-block inclusive + block sums,
// scanB -> exclusive block offsets. rowstart reconstructed inline by readers:
//   rowstart[g+1] = incl[g] + bsum[g>>8]
// ---------------------------------------------------------------------------
__global__ void k_scanA(const int* __restrict__ deg, int* __restrict__ incl,
                        int* __restrict__ bsum, int N) {
    __shared__ int wsum[8];
    int tid = threadIdx.x, lane = tid & 31, warp = tid >> 5;
    int gid = blockIdx.x * 256 + tid;
    int v = (gid < N) ? deg[gid] : 0;
    int x = v;
#pragma unroll
    for (int o = 1; o < 32; o <<= 1) {
        int y = __shfl_up_sync(0xFFFFFFFFu, x, o);
        if (lane >= o) x += y;
    }
    if (lane == 31) wsum[warp] = x;
    __syncthreads();
    if (warp == 0) {
        int s = (lane < 8) ? wsum[lane] : 0;
        int y = s;
#pragma unroll
        for (int o = 1; o < 8; o <<= 1) {
            int z = __shfl_up_sync(0xFFFFFFFFu, y, o);
            if (lane >= o) y += z;
        }
        if (lane < 8) wsum[lane] = y - s;   // exclusive warp offset
    }
    __syncthreads();
    int inclv = x + wsum[warp];
    if (gid < N) incl[gid] = inclv;
    if (tid == 255) bsum[blockIdx.x] = inclv;
}

__global__ void k_scanB(int* __restrict__ bsum, int nb) {
    __shared__ int wsum[8];
    int tid = threadIdx.x, lane = tid & 31, warp = tid >> 5;
    int v = (tid < nb) ? bsum[tid] : 0;
    int x = v;
#pragma unroll
    for (int o = 1; o < 32; o <<= 1) {
        int y = __shfl_up_sync(0xFFFFFFFFu, x, o);
        if (lane >= o) x += y;
    }
    if (lane == 31) wsum[warp] = x;
    __syncthreads();
    if (warp == 0) {
        int s = (lane < 8) ? wsum[lane] : 0;
        int y = s;
#pragma unroll
        for (int o = 1; o < 8; o <<= 1) {
            int z = __shfl_up_sync(0xFFFFFFFFu, y, o);
            if (lane >= o) y += z;
        }
        if (lane < 8) wsum[lane] = y - s;
    }
    __syncthreads();
    if (tid < nb) bsum[tid] = x + wsum[warp] - v;   // exclusive block offset
}

// ---------------------------------------------------------------------------
// CSR fill straight from ei (dtype-branched, clamped), rowstart inline.
// ---------------------------------------------------------------------------
__global__ void k_fill(const void* __restrict__ ei,
                       const int* __restrict__ incl, const int* __restrict__ bsum,
                       int* __restrict__ cursor, int* __restrict__ csr,
                       int E, int N) {
    int e = blockIdx.x * blockDim.x + threadIdx.x;
    if (e >= E) return;
    long long s, d;
    if (g_is64) {
        const long long* p = (const long long*)ei;
        s = p[e];
        d = p[(size_t)E + e];
    } else {
        const int* p = (const int*)ei;
        s = p[e];
        d = p[(size_t)E + e];
    }
    int si = (int)min(max(s, 0LL), (long long)(N - 1));
    int di = (int)min(max(d, 0LL), (long long)(N - 1));
    int rs = (di > 0) ? (incl[di - 1] + bsum[(di - 1) >> 8]) : 0;
    int pos = rs + atomicAdd(&cursor[di], 1);
    csr[pos] = si;
}

// ---------------------------------------------------------------------------
// Fused (logmap+) HMMA GEMM.
// first=1: load fp32 x_hyp, apply logmap, write xt16 + As.
// first=0: load fp16 xt16 (already the tangent vector, written by the
//          previous layer's aggfinal) straight into As — no logmap needed.
// Block: 128 rows x 128 cols, 8 warps; Bs pitch 40 halves (conflict-free);
// W register-prefetch; B fragments via ldmatrix.x4.
// Block 0 thread 0 also resets the agg row cursor.
// ---------------------------------------------------------------------------
__global__ void __launch_bounds__(256) k_gemm_fused(
        const float* __restrict__ xin, const float* __restrict__ W,
        const float* __restrict__ b, __half2* __restrict__ xt16,
        __half2* __restrict__ xl16, const float* __restrict__ curv,
        int l, int N, int first) {
    __shared__ __half As[128][136];   // 34816 B
    __shared__ __half Bs[128][40];    // 10240 B  (total 44 KB)
    int tid = threadIdx.x;
    int lane = tid & 31;
    int wid = tid >> 5;
    int row0 = blockIdx.x * 128;
    int m0 = wid * 16;

    if (blockIdx.x == 0 && tid == 0) g_rowcur = 0u;   // reset agg cursor

    if (first) {
        float c = clip_c(curv[l]);
        float K = 1.0f / c;
        float sqrtK = sqrtf(K);
#pragma unroll
        for (int i = 0; i < 16; i++) {
            int row = m0 + i;
            int grow = row0 + row;
            float4 v = make_float4(0.f, 0.f, 0.f, 0.f);
            if (grow < N)
                v = __ldg(reinterpret_cast<const float4*>(xin + (size_t)grow * D) + lane);
            float ss = v.x * v.x + v.y * v.y + v.z * v.z + v.w * v.w;
            ss = warp_sum(ss);
            float xnorm = sqrtf(ss);
            float t = sqrtf(K + ss);
            float theta = acoshf(fmaxf(t / sqrtK, 1.0f + 1e-7f));
            float s = sqrtK * theta / fmaxf(xnorm, 1e-7f);
            v.x *= s; v.y *= s; v.z *= s; v.w *= s;
            __half2 h0 = __float22half2_rn(make_float2(v.x, v.y));
            __half2 h1 = __float22half2_rn(make_float2(v.z, v.w));
            uint2 u;
            u.x = *reinterpret_cast<unsigned*>(&h0);
            u.y = *reinterpret_cast<unsigned*>(&h1);
            if (grow < N)
                *reinterpret_cast<uint2*>(xt16 + (size_t)grow * (D / 2) + lane * 2) = u;
            *reinterpret_cast<uint2*>(&As[row][lane * 4]) = u;
        }
    } else {
#pragma unroll
        for (int i = 0; i < 16; i++) {
            int row = m0 + i;
            int grow = row0 + row;
            uint2 u = make_uint2(0u, 0u);
            if (grow < N)
                u = __ldg(reinterpret_cast<const uint2*>(
                    xt16 + (size_t)grow * (D / 2)) + lane);
            *reinterpret_cast<uint2*>(&As[row][lane * 4]) = u;
        }
    }

    float acc[16][4];
#pragma unroll
    for (int nt = 0; nt < 16; nt++)
#pragma unroll
        for (int q = 0; q < 4; q++) acc[nt][q] = 0.0f;

    // ldmatrix lane address components
    int a_rr = lane & 7;
    int a_sel = lane >> 3;                  // 0..3
    int a_row = m0 + a_rr + ((a_sel & 1) ? 8 : 0);
    int a_koff = (a_sel >> 1) ? 8 : 0;
    int b_row2 = (lane & 7) + ((lane & 16) ? 8 : 0);
    int b_col2 = (lane & 8) ? 8 : 0;

    // W staging assignment: thread -> row j, k-half
    int wj = tid >> 1;
    int wkh = (tid & 1) * 16;

    // prefetch W chunk 0 into registers
    float4 wreg[4];
    {
        const float4* wp = reinterpret_cast<const float4*>(&W[(size_t)wj * D + wkh]);
#pragma unroll
        for (int p = 0; p < 4; p++) wreg[p] = __ldg(wp + p);
    }

    for (int kc = 0; kc < 4; kc++) {
        __syncthreads();   // previous Bs consumed; kc=0 also covers As writes
        // store registered W chunk to Bs (fp16)
        {
            __half2 h0 = __float22half2_rn(make_float2(wreg[0].x, wreg[0].y));
            __half2 h1 = __float22half2_rn(make_float2(wreg[0].z, wreg[0].w));
            __half2 h2 = __float22half2_rn(make_float2(wreg[1].x, wreg[1].y));
            __half2 h3 = __float22half2_rn(make_float2(wreg[1].z, wreg[1].w));
            __half2 h4 = __float22half2_rn(make_float2(wreg[2].x, wreg[2].y));
            __half2 h5 = __float22half2_rn(make_float2(wreg[2].z, wreg[2].w));
            __half2 h6 = __float22half2_rn(make_float2(wreg[3].x, wreg[3].y));
            __half2 h7 = __float22half2_rn(make_float2(wreg[3].z, wreg[3].w));
            uint4 u0, u1;
            u0.x = *reinterpret_cast<unsigned*>(&h0);
            u0.y = *reinterpret_cast<unsigned*>(&h1);
            u0.z = *reinterpret_cast<unsigned*>(&h2);
            u0.w = *reinterpret_cast<unsigned*>(&h3);
            u1.x = *reinterpret_cast<unsigned*>(&h4);
            u1.y = *reinterpret_cast<unsigned*>(&h5);
            u1.z = *reinterpret_cast<unsigned*>(&h6);
            u1.w = *reinterpret_cast<unsigned*>(&h7);
            *reinterpret_cast<uint4*>(&Bs[wj][wkh + 0]) = u0;
            *reinterpret_cast<uint4*>(&Bs[wj][wkh + 8]) = u1;
        }
        // prefetch next W chunk (latency overlaps sync + MMA below)
        if (kc < 3) {
            const float4* wp = reinterpret_cast<const float4*>(
                &W[(size_t)wj * D + (kc + 1) * 32 + wkh]);
#pragma unroll
            for (int p = 0; p < 4; p++) wreg[p] = __ldg(wp + p);
        }
        __syncthreads();

#pragma unroll
        for (int s = 0; s < 2; s++) {
            int kg = kc * 32 + s * 16;      // global k for A
            int ks = s * 16;                // chunk-local k for B
            unsigned a0, a1, a2, a3;
            unsigned aaddr = smem_u32(&As[a_row][kg + a_koff]);
            asm volatile(
                "ldmatrix.sync.aligned.m8n8.x4.shared.b16 {%0,%1,%2,%3}, [%4];"
                : "=r"(a0), "=r"(a1), "=r"(a2), "=r"(a3) : "r"(aaddr));
#pragma unroll
            for (int p = 0; p < 8; p++) {
                unsigned b0, b1, b2, b3;
                unsigned baddr = smem_u32(&Bs[p * 16 + b_row2][ks + b_col2]);
                asm volatile(
                    "ldmatrix.sync.aligned.m8n8.x4.shared.b16 {%0,%1,%2,%3}, [%4];"
                    : "=r"(b0), "=r"(b1), "=r"(b2), "=r"(b3) : "r"(baddr));
                asm volatile(
                    "mma.sync.aligned.m16n8k16.row.col.f32.f16.f16.f32 "
                    "{%0,%1,%2,%3}, {%4,%5,%6,%7}, {%8,%9}, {%0,%1,%2,%3};"
                    : "+f"(acc[2 * p][0]), "+f"(acc[2 * p][1]),
                      "+f"(acc[2 * p][2]), "+f"(acc[2 * p][3])
                    : "r"(a0), "r"(a1), "r"(a2), "r"(a3), "r"(b0), "r"(b1));
                asm volatile(
                    "mma.sync.aligned.m16n8k16.row.col.f32.f16.f16.f32 "
                    "{%0,%1,%2,%3}, {%4,%5,%6,%7}, {%8,%9}, {%0,%1,%2,%3};"
                    : "+f"(acc[2 * p + 1][0]), "+f"(acc[2 * p + 1][1]),
                      "+f"(acc[2 * p + 1][2]), "+f"(acc[2 * p + 1][3])
                    : "r"(a0), "r"(a1), "r"(a2), "r"(a3), "r"(b2), "r"(b3));
            }
        }
    }

    // Epilogue: add bias, convert to fp16, store xl16.
    int gid = lane >> 2;     // C-fragment row group
    int tig = lane & 3;      // C-fragment col pair
    int row1 = row0 + m0 + gid;
    int row2 = row1 + 8;
#pragma unroll
    for (int nt = 0; nt < 16; nt++) {
        int col = nt * 8 + 2 * tig;
        float2 bv = *reinterpret_cast<const float2*>(&b[col]);
        if (row1 < N) {
            __half2 h = __float22half2_rn(
                make_float2(acc[nt][0] + bv.x, acc[nt][1] + bv.y));
            xl16[(size_t)row1 * (D / 2) + (col >> 1)] = h;
        }
        if (row2 < N) {
            __half2 h = __float22half2_rn(
                make_float2(acc[nt][2] + bv.x, acc[nt][3] + bv.y));
            xl16[(size_t)row2 * (D / 2) + (col >> 1)] = h;
        }
    }
}

// ---------------------------------------------------------------------------
// Fused CSR aggregation (fp16 gather, fp32 accumulate) + mean + residual + LN,
// then:
//   final=0: xt16 = logmap_{c_next}(expmap_{c}(y))  — identity when c==c_next
//            (analytic fusion, no hyperbolic point materialized), fp16.
//   final=1: out = expmap_c(y), fp32.
// Dynamic scheduling: warps grab 4-row chunks from a global cursor.
// ---------------------------------------------------------------------------
__global__ void k_aggfinal(const int* __restrict__ incl, const int* __restrict__ bsum,
                           const int* __restrict__ csr,
                           const __half2* __restrict__ xl16,
                           __half2* __restrict__ xt16,
                           const float* __restrict__ gamma, const float* __restrict__ beta,
                           const float* __restrict__ curv, int l,
                           float* __restrict__ out, int N, int final_) {
    int lane = threadIdx.x & 31;
    const uint2* xlu = reinterpret_cast<const uint2*>(xl16);   // 1 uint2 = 4 halves

    float c = clip_c(curv[l]);
    float K = 1.0f / c;
    float sqrtK = sqrtf(K);
    float cnext = final_ ? c : clip_c(curv[l + 1]);
    float4 g = reinterpret_cast<const float4*>(gamma)[lane];
    float4 bb = reinterpret_cast<const float4*>(beta)[lane];

    for (;;) {
        int base;
        if (lane == 0) base = (int)atomicAdd(&g_rowcur, 4u);
        base = __shfl_sync(0xFFFFFFFFu, base, 0);
        if (base >= N) return;
        int wend = base + 4 < N ? base + 4 : N;

        for (int w = base; w < wend; w++) {
            int beg = (w > 0) ? (incl[w - 1] + bsum[(w - 1) >> 8]) : 0;
            int end = incl[w] + bsum[w >> 8];
            float4 acc = make_float4(0.f, 0.f, 0.f, 0.f);

            int e = beg;
            for (; e + 8 <= end; e += 8) {
                int sidx[8];
#pragma unroll
                for (int t = 0; t < 8; t++) sidx[t] = __ldg(&csr[e + t]);
                uint2 q[8];
#pragma unroll
                for (int t = 0; t < 8; t++)
                    q[t] = __ldg(&xlu[(size_t)sidx[t] * 32 + lane]);
#pragma unroll
                for (int t = 0; t < 8; t++) {
                    float2 f0 = __half22float2(*reinterpret_cast<__half2*>(&q[t].x));
                    float2 f1 = __half22float2(*reinterpret_cast<__half2*>(&q[t].y));
                    acc.x += f0.x; acc.y += f0.y; acc.z += f1.x; acc.w += f1.y;
                }
            }
            if (e + 4 <= end) {
                int sidx[4];
#pragma unroll
                for (int t = 0; t < 4; t++) sidx[t] = __ldg(&csr[e + t]);
                uint2 q[4];
#pragma unroll
                for (int t = 0; t < 4; t++)
                    q[t] = __ldg(&xlu[(size_t)sidx[t] * 32 + lane]);
#pragma unroll
                for (int t = 0; t < 4; t++) {
                    float2 f0 = __half22float2(*reinterpret_cast<__half2*>(&q[t].x));
                    float2 f1 = __half22float2(*reinterpret_cast<__half2*>(&q[t].y));
                    acc.x += f0.x; acc.y += f0.y; acc.z += f1.x; acc.w += f1.y;
                }
                e += 4;
            }
            for (; e < end; e++) {
                int s = __ldg(&csr[e]);
                uint2 q = __ldg(&xlu[(size_t)s * 32 + lane]);
                float2 f0 = __half22float2(*reinterpret_cast<__half2*>(&q.x));
                float2 f1 = __half22float2(*reinterpret_cast<__half2*>(&q.y));
                acc.x += f0.x; acc.y += f0.y; acc.z += f1.x; acc.w += f1.y;
            }

            int dg = end - beg;
            float rcn = 1.0f / (float)(dg > 1 ? dg : 1);

            uint2 tu = __ldg(reinterpret_cast<const uint2*>(
                xt16 + (size_t)w * (D / 2)) + lane);
            float2 t0 = __half22float2(*reinterpret_cast<__half2*>(&tu.x));
            float2 t1 = __half22float2(*reinterpret_cast<__half2*>(&tu.y));
            float4 v = make_float4(t0.x + acc.x * rcn, t0.y + acc.y * rcn,
                                   t1.x + acc.z * rcn, t1.y + acc.w * rcn);

            float s1 = v.x + v.y + v.z + v.w;
            float s2 = v.x * v.x + v.y * v.y + v.z * v.z + v.w * v.w;
            s1 = warp_sum(s1);
            s2 = warp_sum(s2);
            float mean = s1 * (1.0f / D);
            float var = s2 * (1.0f / D) - mean * mean;
            float rstd = rsqrtf(var + 1e-5f);

            float4 y = make_float4((v.x - mean) * rstd * g.x + bb.x,
                                   (v.y - mean) * rstd * g.y + bb.y,
                                   (v.z - mean) * rstd * g.z + bb.z,
                                   (v.w - mean) * rstd * g.w + bb.w);

            float ss = y.x * y.x + y.y * y.y + y.z * y.z + y.w * y.w;
            ss = warp_sum(ss);
            float r = sqrtf(ss);

            if (final_) {
                float sc = sqrtK * sinhf(r / sqrtK) / fmaxf(r, 1e-7f);
                float4 o = make_float4(y.x * sc, y.y * sc, y.z * sc, y.w * sc);
                reinterpret_cast<float4*>(out + (size_t)w * D)[lane] = o;
            } else {
                float sc;
                if (c == cnext) {
                    sc = 1.0f;   // logmap_c(expmap_c(y)) == y exactly
                } else {
                    float se = sqrtK * sinhf(r / sqrtK) / fmaxf(r, 1e-7f);
                    float un = se * r;
                    float K1 = 1.0f / cnext;
                    float sk1 = sqrtf(K1);
                    float t = sqrtf(K1 + un * un);
                    float theta = acoshf(fmaxf(t / sk1, 1.0f + 1e-7f));
                    sc = se * sk1 * theta / fmaxf(un, 1e-7f);
                }
                __half2 h0 = __float22half2_rn(make_float2(y.x * sc, y.y * sc));
                __half2 h1 = __float22half2_rn(make_float2(y.z * sc, y.w * sc));
                uint2 u;
                u.x = *reinterpret_cast<unsigned*>(&h0);
                u.y = *reinterpret_cast<unsigned*>(&h1);
                *reinterpret_cast<uint2*>(xt16 + (size_t)w * (D / 2) + lane * 2) = u;
            }
        }
    }
}

// ---------------------------------------------------------------------------
extern "C" void kernel_launch(void* const* d_in, const int* in_sizes, int n_in,
                              void* d_out, int out_size) {
    const float* x_hyp      = (const float*)d_in[0];
    const void*  ei         = d_in[1];
    const float* W          = (const float*)d_in[2];
    const float* b          = (const float*)d_in[3];
    const float* gamma      = (const float*)d_in[4];
    const float* beta       = (const float*)d_in[5];
    const float* curv       = (const float*)d_in[6];

    int N = in_sizes[0] / D;
    int E = in_sizes[1] / 2;
    int L = in_sizes[6];

    __half2 *xl16, *xt16;
    int *deg, *cursor, *incl, *bsum, *csr;
    cudaGetSymbolAddress((void**)&xt16, g_xt16);
    cudaGetSymbolAddress((void**)&xl16, g_xl16);
    cudaGetSymbolAddress((void**)&deg,  g_deg);
    cudaGetSymbolAddress((void**)&cursor, g_cursor);
    cudaGetSymbolAddress((void**)&incl, g_incl);
    cudaGetSymbolAddress((void**)&bsum, g_bsum);
    cudaGetSymbolAddress((void**)&csr,  g_csr);

    int nb = (N + 255) / 256;

    // One-time CSR build.
    k_detect_zero<<<nb, 256>>>((const long long*)ei, E, (long long)N, deg, cursor, N);
    k_hist<<<(E + 255) / 256, 256>>>(ei, deg, E, N);
    k_scanA<<<nb, 256>>>(deg, incl, bsum, N);
    k_scanB<<<1, 256>>>(bsum, nb);
    k_fill<<<(E + 255) / 256, 256>>>(ei, incl, bsum, cursor, csr, E, N);

    for (int l = 0; l < L; l++) {
        k_gemm_fused<<<(N + 127) / 128, 256>>>(x_hyp, W + (size_t)l * D * D,
                                               b + (size_t)l * D, xt16, xl16,
                                               curv, l, N, l == 0 ? 1 : 0);
        int fin = (l == L - 1) ? 1 : 0;
        k_aggfinal<<<1184, 256>>>(incl, bsum, csr, xl16, xt16,
                                  gamma + (size_t)l * D, beta + (size_t)l * D,
                                  curv, l, (float*)d_out, N, fin);
    }
}